// round 7
// baseline (speedup 1.0000x reference)
#include <cuda_runtime.h>
#include <math.h>
#include <stdint.h>

#define D_MODEL 512
#define F_FF    2048
#define N_EXP   8
#define N_TOK   8192
#define N_ASSIGN (N_TOK * 2)
#define NT_TILES 160
#define BM 128
#define BN 64
#define QMAX 16256.0f    // so a0 <= 127 after (q+64)>>7

#define OUT_LOGITS ((size_t)N_TOK * D_MODEL)
#define OUT_PROBS  (OUT_LOGITS + (size_t)N_TOK * N_EXP)
#define OUT_Z      (OUT_PROBS + (size_t)N_TOK * N_EXP)
#define OUT_LB     (OUT_Z + 1)
#define OUT_LOAD   (OUT_LB + 1)
#define OUT_CNT    (OUT_LOAD + N_EXP)

// ---------------- static scratch ----------------
__device__ char  g_tq0[N_TOK * D_MODEL];
__device__ char  g_tq1[N_TOK * D_MODEL];
__device__ float g_sTok[N_TOK];
__device__ char  g_w1q0[N_EXP * F_FF * D_MODEL];   // [E][F][D]
__device__ char  g_w1q1[N_EXP * F_FF * D_MODEL];
__device__ float g_s1[N_EXP * F_FF];
__device__ char  g_w2q0[N_EXP * D_MODEL * F_FF];   // [E][D][F]
__device__ char  g_w2q1[N_EXP * D_MODEL * F_FF];
__device__ float g_s2[N_EXP * D_MODEL];
__device__ float g_hidden[(size_t)(N_ASSIGN + BM) * F_FF];
__device__ char  g_hq0[(size_t)(N_ASSIGN + BM) * F_FF];
__device__ char  g_hq1[(size_t)(N_ASSIGN + BM) * F_FF];
__device__ float g_sH[N_ASSIGN + BM];
__device__ float g_y[(size_t)(N_ASSIGN + BM) * D_MODEL];
__device__ int   g_tok[N_ASSIGN + BM];
__device__ int   g_pos[N_ASSIGN];
__device__ int   g_topk_idx[N_ASSIGN];
__device__ float g_topk_w[N_ASSIGN];
__device__ int   g_cursor[N_EXP];
__device__ int   g_tile_e[NT_TILES];
__device__ int   g_tile_p0[NT_TILES];
__device__ int   g_tile_rows[NT_TILES];

// ---------------- PTX helpers (baseline ISA only) ----------------
__device__ __forceinline__ uint32_t smem_u32(const void* p) {
    uint32_t a;
    asm("{ .reg .u64 t; cvta.to.shared.u64 t, %1; cvt.u32.u64 %0, t; }" : "=r"(a) : "l"(p));
    return a;
}
#define CP_ASYNC16(dst, src) \
    asm volatile("cp.async.cg.shared.global [%0], [%1], 16;" :: "r"(dst), "l"(src) : "memory")
#define CP_COMMIT() asm volatile("cp.async.commit_group;" ::: "memory")
#define CP_WAIT1()  asm volatile("cp.async.wait_group 1;" ::: "memory")
#define CP_WAIT0()  asm volatile("cp.async.wait_group 0;" ::: "memory")

__device__ __forceinline__ void ldsm_x4(uint32_t addr, uint32_t& r0, uint32_t& r1,
                                        uint32_t& r2, uint32_t& r3) {
    asm volatile("ldmatrix.sync.aligned.m8n8.x4.shared.b16 {%0,%1,%2,%3}, [%4];"
        : "=r"(r0), "=r"(r1), "=r"(r2), "=r"(r3) : "r"(addr));
}
__device__ __forceinline__ void mma_s8(int* d, const uint32_t* a, uint32_t b0, uint32_t b1) {
    asm volatile(
        "mma.sync.aligned.m16n8k32.row.col.s32.s8.s8.s32 "
        "{%0,%1,%2,%3}, {%4,%5,%6,%7}, {%8,%9}, {%0,%1,%2,%3};"
        : "+r"(d[0]), "+r"(d[1]), "+r"(d[2]), "+r"(d[3])
        : "r"(a[0]), "r"(a[1]), "r"(a[2]), "r"(a[3]), "r"(b0), "r"(b1));
}
__device__ __forceinline__ float gelu_f(float x) {
    const float c = 0.7978845608028654f;
    float x3 = x * x * x;
    return 0.5f * x * (1.0f + tanhf(c * (x + 0.044715f * x3)));
}
// two-limb quantize: q = round(x*inv), a0=(q+64)>>7, a1=q-(a0<<7)
__device__ __forceinline__ void quant2(float x, float inv, int& a0, int& a1) {
    int q = __float2int_rn(x * inv);
    a0 = (q + 64) >> 7;
    a1 = q - (a0 << 7);
}

// ================ prep: gating + token quantization (1024 blocks) ================
__global__ __launch_bounds__(256) void prep_kernel(
    const float* __restrict__ tokens, const float* __restrict__ gate_w,
    float* __restrict__ out)
{
    __shared__ float gwT[N_EXP * D_MODEL];
    int t = threadIdx.x;
    for (int i = t; i < D_MODEL * N_EXP; i += 256) {
        int d = i >> 3, e = i & 7;
        gwT[e * 512 + d] = gate_w[i];
    }
    __syncthreads();

    int warp = t >> 5, lane = t & 31;
    int n = blockIdx.x * 8 + warp;
    const float* x = tokens + (size_t)n * D_MODEL;

    float acc[8] = {0.f,0.f,0.f,0.f,0.f,0.f,0.f,0.f};
    float amax = 0.0f;
    for (int d = lane; d < D_MODEL; d += 32) {
        float xv = x[d];
        amax = fmaxf(amax, fabsf(xv));
        #pragma unroll
        for (int e = 0; e < 8; e++) acc[e] = fmaf(xv, gwT[e * 512 + d], acc[e]);
    }
    #pragma unroll
    for (int e = 0; e < 8; e++) {
        #pragma unroll
        for (int o = 16; o; o >>= 1)
            acc[e] += __shfl_down_sync(0xffffffffu, acc[e], o);
    }
    #pragma unroll
    for (int o = 16; o; o >>= 1)
        amax = fmaxf(amax, __shfl_xor_sync(0xffffffffu, amax, o));

    float s = fmaxf(amax, 1e-30f) / QMAX;
    float inv = 1.0f / s;
    if (lane == 0) g_sTok[n] = s;

    // quantize 16 consecutive elems per lane -> packed 16B per plane
    {
        int d0 = lane * 16;
        uint32_t w0[4], w1p[4];
        #pragma unroll
        for (int g = 0; g < 4; g++) {
            uint32_t p0 = 0, p1 = 0;
            #pragma unroll
            for (int j = 0; j < 4; j++) {
                int a0, a1;
                quant2(x[d0 + g * 4 + j], inv, a0, a1);
                p0 |= (uint32_t)(a0 & 0xFF) << (8 * j);
                p1 |= (uint32_t)(a1 & 0xFF) << (8 * j);
            }
            w0[g] = p0; w1p[g] = p1;
        }
        uint32_t* o0 = (uint32_t*)(g_tq0 + (size_t)n * D_MODEL + d0);
        uint32_t* o1 = (uint32_t*)(g_tq1 + (size_t)n * D_MODEL + d0);
        #pragma unroll
        for (int g = 0; g < 4; g++) { o0[g] = w0[g]; o1[g] = w1p[g]; }
    }

    if (lane == 0) {
        float m = acc[0];
        #pragma unroll
        for (int e = 1; e < 8; e++) m = fmaxf(m, acc[e]);
        float p[8], sum = 0.0f;
        #pragma unroll
        for (int e = 0; e < 8; e++) { p[e] = expf(acc[e] - m); sum += p[e]; }
        float invs = 1.0f / sum;
        #pragma unroll
        for (int e = 0; e < 8; e++) p[e] *= invs;

        float* gl = out + OUT_LOGITS + (size_t)n * N_EXP;
        float* pr = out + OUT_PROBS  + (size_t)n * N_EXP;
        #pragma unroll
        for (int e = 0; e < 8; e++) { gl[e] = acc[e]; pr[e] = p[e]; }

        int i0 = 0; float m0 = p[0];
        #pragma unroll
        for (int e = 1; e < 8; e++) if (p[e] > m0) { m0 = p[e]; i0 = e; }
        int i1 = (i0 == 0) ? 1 : 0; float m1 = p[i1];
        #pragma unroll
        for (int e = 0; e < 8; e++)
            if (e != i0 && p[e] > m1) { m1 = p[e]; i1 = e; }
        float ws = m0 + m1;
        g_topk_idx[2 * n]     = i0;
        g_topk_idx[2 * n + 1] = i1;
        g_topk_w[2 * n]       = m0 / ws;
        g_topk_w[2 * n + 1]   = m1 / ws;
    }
}

// ================ weight scales: 80 blocks ================
__global__ __launch_bounds__(256) void wscale_kernel(
    const float* __restrict__ w1, const float* __restrict__ w2)
{
    int b = blockIdx.x, t = threadIdx.x;
    if (b < 64) {                       // w1: max over d of |w1[e][d][f]|
        int e = b >> 3, f = (b & 7) * 256 + t;
        float m = 1e-30f;
        const float* base = w1 + (size_t)e * D_MODEL * F_FF + f;
        for (int d = 0; d < D_MODEL; d++)
            m = fmaxf(m, fabsf(base[(size_t)d * F_FF]));
        g_s1[e * F_FF + f] = m / QMAX;
    } else {                            // w2: max over f of |w2[e][f][d]|
        int idx = b - 64;
        int e = idx >> 1, d = (idx & 1) * 256 + t;
        float m = 1e-30f;
        const float* base = w2 + (size_t)e * F_FF * D_MODEL + d;
        for (int f = 0; f < F_FF; f++)
            m = fmaxf(m, fabsf(base[(size_t)f * D_MODEL]));
        g_s2[e * D_MODEL + d] = m / QMAX;
    }
}

// ================ weight transpose + quantize: 16384 blocks ================
__global__ __launch_bounds__(256) void wquant_kernel(
    const float* __restrict__ w1, const float* __restrict__ w2)
{
    __shared__ float tile[32][33];
    int b = blockIdx.x;
    int tx = threadIdx.x & 31, ty = threadIdx.x >> 5;
    if (b < 8192) {     // w1 [E][D][F] -> planes [E][F][D]
        int e = b >> 10, rem = b & 1023;
        int fblk = rem & 63, dblk = rem >> 6;
        int f0 = fblk * 32, d0 = dblk * 32;
        const float* src = w1 + (size_t)e * D_MODEL * F_FF;
        #pragma unroll
        for (int i = ty; i < 32; i += 8)
            tile[i][tx] = src[(size_t)(d0 + i) * F_FF + f0 + tx];
        __syncthreads();
        #pragma unroll
        for (int i = ty; i < 32; i += 8) {
            int f = f0 + i;
            float inv = 1.0f / g_s1[e * F_FF + f];
            float v = tile[tx][i];
            int a0, a1; quant2(v, inv, a0, a1);
            size_t o = ((size_t)e * F_FF + f) * D_MODEL + d0 + tx;
            g_w1q0[o] = (char)a0;
            g_w1q1[o] = (char)a1;
        }
    } else {            // w2 [E][F][D] -> planes [E][D][F]
        int idx = b - 8192;
        int e = idx >> 10, rem = idx & 1023;
        int fblk = rem >> 4, dblk = rem & 15;
        int f0 = fblk * 32, d0 = dblk * 32;
        const float* src = w2 + (size_t)e * F_FF * D_MODEL;
        #pragma unroll
        for (int i = ty; i < 32; i += 8)
            tile[i][tx] = src[(size_t)(f0 + i) * D_MODEL + d0 + tx];   // tile[fi][di]
        __syncthreads();
        #pragma unroll
        for (int i = ty; i < 32; i += 8) {
            int d = d0 + i;
            float inv = 1.0f / g_s2[e * D_MODEL + d];
            float v = tile[tx][i];
            int a0, a1; quant2(v, inv, a0, a1);
            size_t o = ((size_t)e * D_MODEL + d) * F_FF + f0 + tx;
            g_w2q0[o] = (char)a0;
            g_w2q1[o] = (char)a1;
        }
    }
}

// ================ finalize_scan ================
__global__ __launch_bounds__(1024) void finalize_scan(float* __restrict__ out) {
    __shared__ int   s_cnt[N_EXP];
    __shared__ float s_load[N_EXP];
    __shared__ float s_z;
    int t = threadIdx.x;
    if (t < N_EXP) { s_cnt[t] = 0; s_load[t] = 0.0f; }
    if (t == 0) s_z = 0.0f;
    __syncthreads();

    int lc[N_EXP] = {0,0,0,0,0,0,0,0};
    for (int i = t; i < N_ASSIGN; i += 1024) lc[g_topk_idx[i]]++;
    #pragma unroll
    for (int e = 0; e < N_EXP; e++) if (lc[e]) atomicAdd(&s_cnt[e], lc[e]);

    float ls[N_EXP] = {0,0,0,0,0,0,0,0};
    float z = 0.0f;
    for (int n = t; n < N_TOK; n += 1024) {
        const float* pr = out + OUT_PROBS  + (size_t)n * N_EXP;
        const float* gl = out + OUT_LOGITS + (size_t)n * N_EXP;
        float m = gl[0];
        #pragma unroll
        for (int e = 1; e < 8; e++) m = fmaxf(m, gl[e]);
        float s = 0.0f;
        #pragma unroll
        for (int e = 0; e < 8; e++) { s += expf(gl[e] - m); ls[e] += pr[e]; }
        float lse = m + logf(s);
        z += lse * lse;
    }
    #pragma unroll
    for (int e = 0; e < N_EXP; e++) atomicAdd(&s_load[e], ls[e]);
    atomicAdd(&s_z, z);
    __syncthreads();

    if (t == 0) {
        int off = 0;
        float lb = 0.0f;
        int tcount = 0;
        for (int e = 0; e < N_EXP; e++) {
            g_cursor[e] = off;
            float load = s_load[e] / (float)N_TOK;
            out[OUT_LOAD + e] = load;
            out[OUT_CNT + e]  = (float)s_cnt[e];
            lb += ((float)s_cnt[e] / (float)N_ASSIGN) * load;
            for (int r = 0; r < s_cnt[e]; r += BM) {
                g_tile_e[tcount]    = e;
                g_tile_p0[tcount]   = off + r;
                int rem = s_cnt[e] - r;
                g_tile_rows[tcount] = rem < BM ? rem : BM;
                tcount++;
            }
            off += s_cnt[e];
        }
        for (int i = tcount; i < NT_TILES; i++) g_tile_rows[i] = 0;
        out[OUT_LB] = (float)N_EXP * lb;
        out[OUT_Z]  = s_z / (float)N_TOK;
    }
}

// ---------------- scatter ----------------
__global__ void scatter_kernel() {
    int n = blockIdx.x * blockDim.x + threadIdx.x;
    if (n >= N_TOK) return;
    #pragma unroll
    for (int k = 0; k < 2; k++) {
        int e = g_topk_idx[2 * n + k];
        int pos = atomicAdd(&g_cursor[e], 1);
        g_tok[pos] = n;
        g_pos[2 * n + k] = pos;
    }
}

// =============== int8 two-limb GEMM kernels ===============
// CTA 128x64, 8 warps = 4(M) x 2(N), warp tile 32x32, BK=32 (k32 per stage), 3-stage.
// smem row: [limb0 32B][limb1 32B][pad 16B] = 80B stride (ldsm conflict-free).
#define ROWB 80
#define SA_ST (BM * ROWB)     // 10240
#define SB_ST (BN * ROWB)     // 5120

struct GemmSmem {
    char A[3][SA_ST];
    char B[3][SB_ST];
    int   tok[BM];
    float sa[BM];
    float sb[BN];
    float bias[BN];
};

// GEMM1: hidden = gelu( sA*sB*(16384*I00 + 128*Imid) + b1 )  -> g_hidden fp32
__global__ __launch_bounds__(256, 2) void gemm1_mma(const float* __restrict__ b1) {
    int tile = blockIdx.x;
    int rows = g_tile_rows[tile];
    if (rows == 0) return;
    int e = g_tile_e[tile], p0 = g_tile_p0[tile];
    int c0 = blockIdx.y * BN;

    __shared__ GemmSmem sm;
    int t = threadIdx.x, wid = t >> 5, lane = t & 31;

    if (t < BM) {
        int rr = (t < rows) ? t : (rows - 1);
        int tok = g_tok[p0 + rr];
        sm.tok[t] = tok;
        sm.sa[t]  = g_sTok[tok];
    }
    if (t < BN) {
        sm.sb[t]   = g_s1[e * F_FF + c0 + t];
        sm.bias[t] = b1[(size_t)e * F_FF + c0 + t];
    }
    __syncthreads();

    uint32_t sA[3] = {smem_u32(sm.A[0]), smem_u32(sm.A[1]), smem_u32(sm.A[2])};
    uint32_t sB[3] = {smem_u32(sm.B[0]), smem_u32(sm.B[1]), smem_u32(sm.B[2])};

    // per-thread load assignment
    int arow = t & 127, ah = t >> 7;                   // A: row, 16B-half; limbs via it
    const char* srcA0 = g_tq0 + (size_t)sm.tok[arow] * D_MODEL + ah * 16;
    const char* srcA1 = g_tq1 + (size_t)sm.tok[arow] * D_MODEL + ah * 16;
    uint32_t dstA0 = (uint32_t)(arow * ROWB + ah * 16);
    uint32_t dstA1 = dstA0 + 32;
    int brow = t & 63, brest = t >> 6;                 // B: 1 chunk/thread
    int blimb = brest >> 1, bh = brest & 1;
    const char* srcB = (blimb ? g_w1q1 : g_w1q0)
                     + ((size_t)e * F_FF + c0 + brow) * D_MODEL + bh * 16;
    uint32_t dstB = (uint32_t)(brow * ROWB + blimb * 32 + bh * 16);

    auto loadStage = [&](int kt, int st) {
        int kk = kt * 32;
        CP_ASYNC16(sA[st] + dstA0, srcA0 + kk);
        CP_ASYNC16(sA[st] + dstA1, srcA1 + kk);
        CP_ASYNC16(sB[st] + dstB,  srcB  + kk);
        CP_COMMIT();
    };

    int wm = (wid >> 1) * 32, wn = (wid & 1) * 32;
    uint32_t aOff = (uint32_t)((wm + (lane & 15)) * ROWB + (lane >> 4) * 16);
    uint32_t bOff = (uint32_t)((wn + (lane & 7) + ((lane >> 4) << 3)) * ROWB
                               + ((lane >> 3) & 1) * 16);

    int accH[2][4][4], accM[2][4][4];
    #pragma unroll
    for (int i = 0; i < 2; i++)
        #pragma unroll
        for (int j = 0; j < 4; j++)
            #pragma unroll
            for (int r = 0; r < 4; r++) { accH[i][j][r] = 0; accM[i][j][r] = 0; }

    const int KT = D_MODEL / 32;   // 16
    loadStage(0, 0);
    loadStage(1, 1);
    #pragma unroll 1
    for (int kt = 0; kt < KT; kt++) {
        if (kt + 1 < KT) { CP_WAIT1(); } else { CP_WAIT0(); }
        __syncthreads();
        if (kt + 2 < KT) loadStage(kt + 2, (kt + 2) % 3);
        int st = kt % 3;
        uint32_t aB = sA[st] + aOff, bB = sB[st] + bOff;

        uint32_t a0[2][4], a1[2][4];       // [mt][frag]
        uint32_t b0[2][4], b1f[2][4];      // [p(n16)][frag]
        #pragma unroll
        for (int mt = 0; mt < 2; mt++) {
            ldsm_x4(aB + mt * 16 * ROWB,      a0[mt][0], a0[mt][1], a0[mt][2], a0[mt][3]);
            ldsm_x4(aB + mt * 16 * ROWB + 32, a1[mt][0], a1[mt][1], a1[mt][2], a1[mt][3]);
        }
        #pragma unroll
        for (int p = 0; p < 2; p++) {
            ldsm_x4(bB + p * 16 * ROWB,      b0[p][0],  b0[p][1],  b0[p][2],  b0[p][3]);
            ldsm_x4(bB + p * 16 * ROWB + 32, b1f[p][0], b1f[p][1], b1f[p][2], b1f[p][3]);
        }
        #pragma unroll
        for (int mt = 0; mt < 2; mt++) {
            #pragma unroll
            for (int nt = 0; nt < 4; nt++) {
                int p = nt >> 1, sub = nt & 1;
                uint32_t bl0 = b0[p][sub * 2],  bl1 = b0[p][sub * 2 + 1];
                uint32_t bm0 = b1f[p][sub * 2], bm1 = b1f[p][sub * 2 + 1];
                mma_s8(accH[mt][nt], a0[mt], bl0, bl1);   // I00
                mma_s8(accM[mt][nt], a0[mt], bm0, bm1);   // I01
                mma_s8(accM[mt][nt], a1[mt], bl0, bl1);   // I10
            }
        }
    }

    int qrow = lane >> 2, qcol = (lane & 3) * 2;
    #pragma unroll
    for (int mt = 0; mt < 2; mt++) {
        #pragma unroll
        for (int half = 0; half < 2; half++) {
            int m = wm + mt * 16 + qrow + 8 * half;
            if (m >= rows) continue;
            float sa = sm.sa[m];
            size_t orow = (size_t)(p0 + m) * F_FF + c0;
            #pragma unroll
            for (int nt = 0; nt < 4; nt++) {
                int nl = wn + nt * 8 + qcol;
                float x0 = 16384.0f * (float)accH[mt][nt][2 * half]
                         + 128.0f   * (float)accM[mt][nt][2 * half];
                float x1 = 16384.0f * (float)accH[mt][nt][2 * half + 1]
                         + 128.0f   * (float)accM[mt][nt][2 * half + 1];
                float2 v;
                v.x = gelu_f(sa * sm.sb[nl]     * x0 + sm.bias[nl]);
                v.y = gelu_f(sa * sm.sb[nl + 1] * x1 + sm.bias[nl + 1]);
                *(float2*)(g_hidden + orow + nl) = v;
            }
        }
    }
}

// quantize hidden rows -> limbs + scale (block per row)
__global__ __launch_bounds__(256) void quant_hidden(void) {
    __shared__ float s_max[32];
    int r = blockIdx.x, t = threadIdx.x;
    const float* row = g_hidden + (size_t)r * F_FF;
    float m = 1e-30f;
    #pragma unroll
    for (int j = 0; j < 8; j++) m = fmaxf(m, fabsf(row[t + j * 256]));
    #pragma unroll
    for (int o = 16; o; o >>= 1) m = fmaxf(m, __shfl_xor_sync(0xffffffffu, m, o));
    if ((t & 31) == 0) s_max[t >> 5] = m;
    __syncthreads();
    if (t < 32) {
        float v = (t < 8) ? s_max[t] : 0.0f;
        #pragma unroll
        for (int o = 4; o; o >>= 1) v = fmaxf(v, __shfl_xor_sync(0xffffffffu, v, o));
        if (t == 0) { s_max[0] = v; g_sH[r] = v / QMAX; }
    }
    __syncthreads();
    float inv = QMAX / s_max[0];

    int c0 = t * 8;   // 8 consecutive elems
    uint32_t p0[2], p1[2];
    #pragma unroll
    for (int g = 0; g < 2; g++) {
        uint32_t w0 = 0, w1 = 0;
        #pragma unroll
        for (int j = 0; j < 4; j++) {
            int a0, a1;
            quant2(row[c0 + g * 4 + j], inv, a0, a1);
            w0 |= (uint32_t)(a0 & 0xFF) << (8 * j);
            w1 |= (uint32_t)(a1 & 0xFF) << (8 * j);
        }
        p0[g] = w0; p1[g] = w1;
    }
    uint32_t* o0 = (uint32_t*)(g_hq0 + (size_t)r * F_FF + c0);
    uint32_t* o1 = (uint32_t*)(g_hq1 + (size_t)r * F_FF + c0);
    o0[0] = p0[0]; o0[1] = p0[1];
    o1[0] = p1[0]; o1[1] = p1[1];
}

// GEMM2: y = sH*s2*(16384*I00 + 128*Imid) + b2  -> g_y fp32
__global__ __launch_bounds__(256, 2) void gemm2_mma(const float* __restrict__ b2) {
    int tile = blockIdx.x;
    int rows = g_tile_rows[tile];
    if (rows == 0) return;
    int e = g_tile_e[tile], p0 = g_tile_p0[tile];
    int c0 = blockIdx.y * BN;

    __shared__ GemmSmem sm;
    int t = threadIdx.x, wid = t >> 5, lane = t & 31;

    if (t < BM) sm.sa[t] = g_sH[p0 + t];
    if (t < BN) {
        sm.sb[t]   = g_s2[e * D_MODEL + c0 + t];
        sm.bias[t] = b2[(size_t)e * D_MODEL + c0 + t];
    }
    __syncthreads();

    uint32_t sA[3] = {smem_u32(sm.A[0]), smem_u32(sm.A[1]), smem_u32(sm.A[2])};
    uint32_t sB[3] = {smem_u32(sm.B[0]), smem_u32(sm.B[1]), smem_u32(sm.B[2])};

    int arow = t & 127, ah = t >> 7;
    const char* srcA0 = g_hq0 + (size_t)(p0 + arow) * F_FF + ah * 16;
    const char* srcA1 = g_hq1 + (size_t)(p0 + arow) * F_FF + ah * 16;
    uint32_t dstA0 = (uint32_t)(arow * ROWB + ah * 16);
    uint32_t dstA1 = dstA0 + 32;
    int brow = t & 63, brest = t >> 6;
    int blimb = brest >> 1, bh = brest & 1;
    const char* srcB = (blimb ? g_w2q1 : g_w2q0)
                     + ((size_t)e * D_MODEL + c0 + brow) * F_FF + bh * 16;
    uint32_t dstB = (uint32_t)(brow * ROWB + blimb * 32 + bh * 16);

    auto loadStage = [&](int kt, int st) {
        int kk = kt * 32;
        CP_ASYNC16(sA[st] + dstA0, srcA0 + kk);
        CP_ASYNC16(sA[st] + dstA1, srcA1 + kk);
        CP_ASYNC16(sB[st] + dstB,  srcB  + kk);
        CP_COMMIT();
    };

    int wm = (wid >> 1) * 32, wn = (wid & 1) * 32;
    uint32_t aOff = (uint32_t)((wm + (lane & 15)) * ROWB + (lane >> 4) * 16);
    uint32_t bOff = (uint32_t)((wn + (lane & 7) + ((lane >> 4) << 3)) * ROWB
                               + ((lane >> 3) & 1) * 16);

    int accH[2][4][4], accM[2][4][4];
    #pragma unroll
    for (int i = 0; i < 2; i++)
        #pragma unroll
        for (int j = 0; j < 4; j++)
            #pragma unroll
            for (int r = 0; r < 4; r++) { accH[i][j][r] = 0; accM[i][j][r] = 0; }

    const int KT = F_FF / 32;   // 64
    loadStage(0, 0);
    loadStage(1, 1);
    #pragma unroll 1
    for (int kt = 0; kt < KT; kt++) {
        if (kt + 1 < KT) { CP_WAIT1(); } else { CP_WAIT0(); }
        __syncthreads();
        if (kt + 2 < KT) loadStage(kt + 2, (kt + 2) % 3);
        int st = kt % 3;
        uint32_t aB = sA[st] + aOff, bB = sB[st] + bOff;

        uint32_t a0[2][4], a1[2][4];
        uint32_t b0[2][4], b1f[2][4];
        #pragma unroll
        for (int mt = 0; mt < 2; mt++) {
            ldsm_x4(aB + mt * 16 * ROWB,      a0[mt][0], a0[mt][1], a0[mt][2], a0[mt][3]);
            ldsm_x4(aB + mt * 16 * ROWB + 32, a1[mt][0], a1[mt][1], a1[mt][2], a1[mt][3]);
        }
        #pragma unroll
        for (int p = 0; p < 2; p++) {
            ldsm_x4(bB + p * 16 * ROWB,      b0[p][0],  b0[p][1],  b0[p][2],  b0[p][3]);
            ldsm_x4(bB + p * 16 * ROWB + 32, b1f[p][0], b1f[p][1], b1f[p][2], b1f[p][3]);
        }
        #pragma unroll
        for (int mt = 0; mt < 2; mt++) {
            #pragma unroll
            for (int nt = 0; nt < 4; nt++) {
                int p = nt >> 1, sub = nt & 1;
                uint32_t bl0 = b0[p][sub * 2],  bl1 = b0[p][sub * 2 + 1];
                uint32_t bm0 = b1f[p][sub * 2], bm1 = b1f[p][sub * 2 + 1];
                mma_s8(accH[mt][nt], a0[mt], bl0, bl1);
                mma_s8(accM[mt][nt], a0[mt], bm0, bm1);
                mma_s8(accM[mt][nt], a1[mt], bl0, bl1);
            }
        }
    }

    int qrow = lane >> 2, qcol = (lane & 3) * 2;
    #pragma unroll
    for (int mt = 0; mt < 2; mt++) {
        #pragma unroll
        for (int half = 0; half < 2; half++) {
            int m = wm + mt * 16 + qrow + 8 * half;
            if (m >= rows) continue;
            float sa = sm.sa[m];
            size_t orow = (size_t)(p0 + m) * D_MODEL + c0;
            #pragma unroll
            for (int nt = 0; nt < 4; nt++) {
                int nl = wn + nt * 8 + qcol;
                float x0 = 16384.0f * (float)accH[mt][nt][2 * half]
                         + 128.0f   * (float)accM[mt][nt][2 * half];
                float x1 = 16384.0f * (float)accH[mt][nt][2 * half + 1]
                         + 128.0f   * (float)accM[mt][nt][2 * half + 1];
                float2 v;
                v.x = sa * sm.sb[nl]     * x0 + sm.bias[nl];
                v.y = sa * sm.sb[nl + 1] * x1 + sm.bias[nl + 1];
                *(float2*)(g_y + orow + nl) = v;
            }
        }
    }
}

// ---------------- combine ----------------
__global__ __launch_bounds__(128) void combine_kernel(float* __restrict__ out) {
    int n = blockIdx.x;
    int pa = g_pos[2 * n], pb = g_pos[2 * n + 1];
    float w0 = g_topk_w[2 * n], w1 = g_topk_w[2 * n + 1];
    int d = threadIdx.x * 4;
    float4 y0 = *(const float4*)(g_y + (size_t)pa * D_MODEL + d);
    float4 y1 = *(const float4*)(g_y + (size_t)pb * D_MODEL + d);
    float4 r;
    r.x = w0 * y0.x + w1 * y1.x;
    r.y = w0 * y0.y + w1 * y1.y;
    r.z = w0 * y0.z + w1 * y1.z;
    r.w = w0 * y0.w + w1 * y1.w;
    *(float4*)(out + (size_t)n * D_MODEL + d) = r;
}

// ---------------- launch ----------------
extern "C" void kernel_launch(void* const* d_in, const int* in_sizes, int n_in,
                              void* d_out, int out_size) {
    const float* h_t    = (const float*)d_in[0];
    const float* gate_w = (const float*)d_in[1];
    const float* w1     = (const float*)d_in[2];
    const float* b1     = (const float*)d_in[3];
    const float* w2     = (const float*)d_in[4];
    const float* b2     = (const float*)d_in[5];
    float* out = (float*)d_out;

    prep_kernel<<<N_TOK / 8, 256>>>(h_t, gate_w, out);
    wscale_kernel<<<80, 256>>>(w1, w2);
    wquant_kernel<<<16384, 256>>>(w1, w2);
    finalize_scan<<<1, 1024>>>(out);
    scatter_kernel<<<N_TOK / 256, 256>>>();
    gemm1_mma<<<dim3(NT_TILES, F_FF / BN), 256>>>(b1);     // ncu slot: gemm1
    quant_hidden<<<N_ASSIGN, 256>>>();
    gemm2_mma<<<dim3(NT_TILES, D_MODEL / BN), 256>>>(b2);
    combine_kernel<<<N_TOK, 128>>>(out);
}

// round 8
// speedup vs baseline: 2.3512x; 2.3512x over previous
#include <cuda_runtime.h>
#include <cuda_bf16.h>
#include <math.h>
#include <stdint.h>

#define D_MODEL 512
#define F_FF    2048
#define N_EXP   8
#define N_TOK   8192
#define N_ASSIGN (N_TOK * 2)
#define NT_TILES 160
#define BM 128
#define BN 128
#define BK 64            // elems per stage
#define LDAB 144         // bytes per smem row (128B data + 16B pad)
#define NSTAGE 3

#define SA_ST (BM * LDAB)                 // 18432
#define SB_ST (BN * LDAB)                 // 18432
#define STOK_OFF  (6 * SA_ST)             // 110592
#define SBIAS_OFF (STOK_OFF + 512)
#define SMEM_BYTES (SBIAS_OFF + 512)      // 111616

// prep block partition
#define NB_GATE 1024
#define NB_W1T  8192
#define NB_W2T  8192

#define OUT_LOGITS ((size_t)N_TOK * D_MODEL)
#define OUT_PROBS  (OUT_LOGITS + (size_t)N_TOK * N_EXP)
#define OUT_Z      (OUT_PROBS + (size_t)N_TOK * N_EXP)
#define OUT_LB     (OUT_Z + 1)
#define OUT_LOAD   (OUT_LB + 1)
#define OUT_CNT    (OUT_LOAD + N_EXP)

// ---------------- static scratch ----------------
__device__ __nv_bfloat16 g_tok_hi[N_TOK * D_MODEL];
__device__ __nv_bfloat16 g_tok_lo[N_TOK * D_MODEL];
__device__ __nv_bfloat16 g_w1T_hi[N_EXP * F_FF * D_MODEL];   // [E, F, D] K-major
__device__ __nv_bfloat16 g_w1T_lo[N_EXP * F_FF * D_MODEL];
__device__ __nv_bfloat16 g_w2T_hi[N_EXP * D_MODEL * F_FF];   // [E, D, F] K-major
__device__ __nv_bfloat16 g_w2T_lo[N_EXP * D_MODEL * F_FF];
__device__ __nv_bfloat16 g_hid_hi[(N_ASSIGN + BM) * F_FF];
__device__ __nv_bfloat16 g_hid_lo[(N_ASSIGN + BM) * F_FF];
__device__ float g_y[(size_t)(N_ASSIGN + BM) * D_MODEL];
__device__ int   g_tok[N_ASSIGN + BM];
__device__ int   g_pos[N_ASSIGN];
__device__ int   g_topk_idx[N_ASSIGN];
__device__ float g_topk_w[N_ASSIGN];
__device__ int   g_cnt[N_EXP];
__device__ int   g_cursor[N_EXP];
__device__ float g_zsum;
__device__ float g_loadsum[N_EXP];
__device__ int   g_tile_e[NT_TILES];
__device__ int   g_tile_p0[NT_TILES];
__device__ int   g_tile_rows[NT_TILES];

// ---------------- PTX helpers (baseline ISA only) ----------------
__device__ __forceinline__ uint32_t smem_u32(const void* p) {
    uint32_t a;
    asm("{ .reg .u64 t; cvta.to.shared.u64 t, %1; cvt.u32.u64 %0, t; }" : "=r"(a) : "l"(p));
    return a;
}
#define CP_ASYNC16(dst, src) \
    asm volatile("cp.async.cg.shared.global [%0], [%1], 16;" :: "r"(dst), "l"(src) : "memory")
#define CP_COMMIT() asm volatile("cp.async.commit_group;" ::: "memory")
#define CP_WAIT1()  asm volatile("cp.async.wait_group 1;" ::: "memory")
#define CP_WAIT0()  asm volatile("cp.async.wait_group 0;" ::: "memory")

__device__ __forceinline__ void ldsm_x4(uint32_t addr, uint32_t& r0, uint32_t& r1,
                                        uint32_t& r2, uint32_t& r3) {
    asm volatile("ldmatrix.sync.aligned.m8n8.x4.shared.b16 {%0,%1,%2,%3}, [%4];"
        : "=r"(r0), "=r"(r1), "=r"(r2), "=r"(r3) : "r"(addr));
}
__device__ __forceinline__ void mma_bf16(float* d, const uint32_t* a,
                                         uint32_t b0, uint32_t b1) {
    asm volatile(
        "mma.sync.aligned.m16n8k16.row.col.f32.bf16.bf16.f32 "
        "{%0,%1,%2,%3}, {%4,%5,%6,%7}, {%8,%9}, {%0,%1,%2,%3};"
        : "+f"(d[0]), "+f"(d[1]), "+f"(d[2]), "+f"(d[3])
        : "r"(a[0]), "r"(a[1]), "r"(a[2]), "r"(a[3]), "r"(b0), "r"(b1));
}
__device__ __forceinline__ float gelu_f(float x) {
    const float c = 0.7978845608028654f;
    float x3 = x * x * x;
    return 0.5f * x * (1.0f + tanhf(c * (x + 0.044715f * x3)));
}

// ---------------- init ----------------
__global__ void init_kernel() {
    int t = threadIdx.x;
    if (t < N_EXP) { g_cnt[t] = 0; g_loadsum[t] = 0.0f; }
    if (t == 0) g_zsum = 0.0f;
}

// ================ prep: gating(+stats) + token split + weight transposes ================
__device__ __forceinline__ void transpose_split_part(
    float (*tile)[33], const float* __restrict__ in,
    __nv_bfloat16* __restrict__ out_hi, __nv_bfloat16* __restrict__ out_lo,
    int R, int C, int e, int c0, int r0, int tx, int ty)
{
    const float* src = in + (size_t)e * R * C;
    #pragma unroll
    for (int i = ty; i < 32; i += 8)
        tile[i][tx] = src[(size_t)(r0 + i) * C + c0 + tx];
    __syncthreads();
    __nv_bfloat16* dh = out_hi + (size_t)e * R * C;
    __nv_bfloat16* dl = out_lo + (size_t)e * R * C;
    #pragma unroll
    for (int i = ty; i < 32; i += 8) {
        float v = tile[tx][i];
        __nv_bfloat16 h = __float2bfloat16(v);
        __nv_bfloat16 l = __float2bfloat16(v - __bfloat162float(h));
        dh[(size_t)(c0 + i) * R + r0 + tx] = h;
        dl[(size_t)(c0 + i) * R + r0 + tx] = l;
    }
}

__global__ __launch_bounds__(256) void prep_kernel(
    const float* __restrict__ tokens, const float* __restrict__ gate_w,
    const float* __restrict__ w1, const float* __restrict__ w2,
    float* __restrict__ out)
{
    __shared__ __align__(16) char sbuf[16384];
    __shared__ float s_load[N_EXP];
    __shared__ int   s_cnt[N_EXP];
    __shared__ float s_z;
    int b = blockIdx.x;
    int t = threadIdx.x;

    if (b >= NB_GATE) {
        float (*tile)[33] = (float(*)[33])sbuf;
        int tx = t & 31, ty = t >> 5;
        if (b < NB_GATE + NB_W1T) {
            int idx = b - NB_GATE;
            int e = idx >> 10, rem = idx & 1023;
            int c0 = (rem & 63) * 32, r0 = (rem >> 6) * 32;
            transpose_split_part(tile, w1, g_w1T_hi, g_w1T_lo, D_MODEL, F_FF, e, c0, r0, tx, ty);
        } else {
            int idx = b - NB_GATE - NB_W1T;
            int e = idx >> 10, rem = idx & 1023;
            int c0 = (rem & 15) * 32, r0 = (rem >> 4) * 32;
            transpose_split_part(tile, w2, g_w2T_hi, g_w2T_lo, F_FF, D_MODEL, e, c0, r0, tx, ty);
        }
        return;
    }

    float* gwT = (float*)sbuf;   // [8][512]
    for (int i = t; i < D_MODEL * N_EXP; i += 256) {
        int d = i >> 3, e = i & 7;
        gwT[e * 512 + d] = gate_w[i];
    }
    if (t < N_EXP) { s_load[t] = 0.0f; s_cnt[t] = 0; }
    if (t == 0) s_z = 0.0f;
    __syncthreads();

    int n0 = b * 8;
    // token hi/lo conversion: 8 tokens x 512 dims = 1024 float4
    {
        const float4* src = (const float4*)(tokens + (size_t)n0 * D_MODEL);
        size_t obase = (size_t)n0 * D_MODEL;
        for (int i = t; i < 1024; i += 256) {
            float4 v = src[i];
            __nv_bfloat16 h0 = __float2bfloat16(v.x), h1 = __float2bfloat16(v.y);
            __nv_bfloat16 h2 = __float2bfloat16(v.z), h3 = __float2bfloat16(v.w);
            __nv_bfloat16 l0 = __float2bfloat16(v.x - __bfloat162float(h0));
            __nv_bfloat16 l1 = __float2bfloat16(v.y - __bfloat162float(h1));
            __nv_bfloat16 l2 = __float2bfloat16(v.z - __bfloat162float(h2));
            __nv_bfloat16 l3 = __float2bfloat16(v.w - __bfloat162float(h3));
            __nv_bfloat162 ph0, ph1, pl0, pl1;
            ph0.x = h0; ph0.y = h1; ph1.x = h2; ph1.y = h3;
            pl0.x = l0; pl0.y = l1; pl1.x = l2; pl1.y = l3;
            ((__nv_bfloat162*)(g_tok_hi + obase))[2*i]   = ph0;
            ((__nv_bfloat162*)(g_tok_hi + obase))[2*i+1] = ph1;
            ((__nv_bfloat162*)(g_tok_lo + obase))[2*i]   = pl0;
            ((__nv_bfloat162*)(g_tok_lo + obase))[2*i+1] = pl1;
        }
    }

    int warp = t >> 5, lane = t & 31;
    int n = n0 + warp;
    const float* x = tokens + (size_t)n * D_MODEL;

    float acc[8] = {0.f,0.f,0.f,0.f,0.f,0.f,0.f,0.f};
    for (int d = lane; d < D_MODEL; d += 32) {
        float xv = x[d];
        #pragma unroll
        for (int e = 0; e < 8; e++) acc[e] = fmaf(xv, gwT[e * 512 + d], acc[e]);
    }
    #pragma unroll
    for (int e = 0; e < 8; e++) {
        #pragma unroll
        for (int o = 16; o; o >>= 1)
            acc[e] += __shfl_down_sync(0xffffffffu, acc[e], o);
    }

    if (lane == 0) {
        float m = acc[0];
        #pragma unroll
        for (int e = 1; e < 8; e++) m = fmaxf(m, acc[e]);
        float p[8], s = 0.0f;
        #pragma unroll
        for (int e = 0; e < 8; e++) { p[e] = expf(acc[e] - m); s += p[e]; }
        float inv = 1.0f / s;
        #pragma unroll
        for (int e = 0; e < 8; e++) p[e] *= inv;

        float* gl = out + OUT_LOGITS + (size_t)n * N_EXP;
        float* pr = out + OUT_PROBS  + (size_t)n * N_EXP;
        #pragma unroll
        for (int e = 0; e < 8; e++) { gl[e] = acc[e]; pr[e] = p[e]; }

        float lse = m + logf(s);
        atomicAdd(&s_z, lse * lse);
        #pragma unroll
        for (int e = 0; e < 8; e++) atomicAdd(&s_load[e], p[e]);

        int i0 = 0; float m0 = p[0];
        #pragma unroll
        for (int e = 1; e < 8; e++) if (p[e] > m0) { m0 = p[e]; i0 = e; }
        int i1 = (i0 == 0) ? 1 : 0; float m1 = p[i1];
        #pragma unroll
        for (int e = 0; e < 8; e++)
            if (e != i0 && p[e] > m1) { m1 = p[e]; i1 = e; }
        float ws = m0 + m1;
        g_topk_idx[2 * n]     = i0;
        g_topk_idx[2 * n + 1] = i1;
        g_topk_w[2 * n]       = m0 / ws;
        g_topk_w[2 * n + 1]   = m1 / ws;
        atomicAdd(&s_cnt[i0], 1);
        atomicAdd(&s_cnt[i1], 1);
    }
    __syncthreads();
    if (t < N_EXP) {
        atomicAdd(&g_cnt[t], s_cnt[t]);
        atomicAdd(&g_loadsum[t], s_load[t]);
    }
    if (t == 0) atomicAdd(&g_zsum, s_z);
}

// ---------------- finalize: offsets, losses, tile map (tiny) ----------------
__global__ void finalize_kernel(float* __restrict__ out) {
    if (threadIdx.x != 0) return;
    int off = 0;
    float lb = 0.0f;
    int tcount = 0;
    for (int e = 0; e < N_EXP; e++) {
        g_cursor[e] = off;
        int cnt = g_cnt[e];
        float load = g_loadsum[e] / (float)N_TOK;
        out[OUT_LOAD + e] = load;
        out[OUT_CNT + e]  = (float)cnt;
        lb += ((float)cnt / (float)N_ASSIGN) * load;
        for (int r = 0; r < cnt; r += BM) {
            g_tile_e[tcount]    = e;
            g_tile_p0[tcount]   = off + r;
            int rem = cnt - r;
            g_tile_rows[tcount] = rem < BM ? rem : BM;
            tcount++;
        }
        off += cnt;
    }
    for (int i = tcount; i < NT_TILES; i++) g_tile_rows[i] = 0;
    out[OUT_LB] = (float)N_EXP * lb;
    out[OUT_Z]  = g_zsum / (float)N_TOK;
}

// ---------------- scatter ----------------
__global__ void scatter_kernel() {
    int n = blockIdx.x * blockDim.x + threadIdx.x;
    if (n >= N_TOK) return;
    #pragma unroll
    for (int k = 0; k < 2; k++) {
        int e = g_topk_idx[2 * n + k];
        int pos = atomicAdd(&g_cursor[e], 1);
        g_tok[pos] = n;
        g_pos[2 * n + k] = pos;
    }
}

// =============== warp-MMA GEMMs: BK=64, 3-stage, fragment double-buffer ===============
// CTA 128x128, 8 warps 2(M)x4(N), warp tile 64x32.

// GEMM1: hidden = gelu(gather(tokens) @ w1T^T + b1) -> split bf16 hi/lo
__global__ __launch_bounds__(256, 2) void gemm1_mma(const float* __restrict__ b1) {
    int tile = blockIdx.x;
    int rows = g_tile_rows[tile];
    if (rows == 0) return;
    int e = g_tile_e[tile], p0 = g_tile_p0[tile];
    int c0 = blockIdx.y * BN;

    extern __shared__ char dyn[];
    int*   s_tok  = (int*)(dyn + STOK_OFF);
    float* s_bias = (float*)(dyn + SBIAS_OFF);

    int t = threadIdx.x, wid = t >> 5, lane = t & 31;
    if (t < BM) {
        int rr = (t < rows) ? t : (rows - 1);
        s_tok[t]  = g_tok[p0 + rr];
        s_bias[t] = b1[(size_t)e * F_FF + c0 + t];
    }
    __syncthreads();

    uint32_t sb = smem_u32(dyn);
    uint32_t sA[3] = {sb, sb + SA_ST, sb + 2 * SA_ST};
    uint32_t sB[3] = {sb + 3 * SA_ST, sb + 3 * SA_ST + SB_ST, sb + 3 * SA_ST + 2 * SB_ST};

    auto loadStage = [&](int kt, int st) {
        int seg = kt >> 3, kk = (kt & 7) * BK;
        const __nv_bfloat16* Ag = (seg < 2) ? g_tok_hi : g_tok_lo;
        const __nv_bfloat16* Bg = (seg == 1) ? g_w1T_lo : g_w1T_hi;
        const __nv_bfloat16* Bbase = Bg + ((size_t)e * F_FF + c0) * D_MODEL + kk;
        #pragma unroll
        for (int it = 0; it < 4; it++) {
            int idx = t + it * 256;
            int row = idx >> 3, c = idx & 7;
            CP_ASYNC16(sA[st] + row * LDAB + c * 16,
                       Ag + (size_t)s_tok[row] * D_MODEL + kk + c * 8);
        }
        #pragma unroll
        for (int it = 0; it < 4; it++) {
            int idx = t + it * 256;
            int row = idx >> 3, c = idx & 7;
            CP_ASYNC16(sB[st] + row * LDAB + c * 16,
                       Bbase + (size_t)row * D_MODEL + c * 8);
        }
        CP_COMMIT();
    };

    int wm = (wid >> 2) * 64, wn = (wid & 3) * 32;
    uint32_t aOff = (uint32_t)((wm + (lane & 15)) * LDAB + (lane >> 4) * 16);
    uint32_t bOff = (uint32_t)((wn + (lane & 15)) * LDAB + (lane >> 4) * 16);

    float acc[4][4][4];
    #pragma unroll
    for (int i = 0; i < 4; i++)
        #pragma unroll
        for (int j = 0; j < 4; j++)
            #pragma unroll
            for (int r = 0; r < 4; r++) acc[i][j][r] = 0.0f;

    const int KT = (D_MODEL / BK) * 3;   // 24
    loadStage(0, 0);
    loadStage(1, 1);

    uint32_t af[2][4][4], bf[2][2][4];
    #pragma unroll 1
    for (int kt = 0; kt < KT; kt++) {
        if (kt + 1 < KT) { CP_WAIT1(); } else { CP_WAIT0(); }
        __syncthreads();
        if (kt + 2 < KT) loadStage(kt + 2, (kt + 2) % 3);
        int st = kt % 3;
        uint32_t aB = sA[st] + aOff, bB = sB[st] + bOff;

        // preload k16 chunk 0
        #pragma unroll
        for (int mt = 0; mt < 4; mt++)
            ldsm_x4(aB + mt * 16 * LDAB, af[0][mt][0], af[0][mt][1], af[0][mt][2], af[0][mt][3]);
        #pragma unroll
        for (int p = 0; p < 2; p++)
            ldsm_x4(bB + p * 16 * LDAB, bf[0][p][0], bf[0][p][1], bf[0][p][2], bf[0][p][3]);

        #pragma unroll
        for (int j = 0; j < 4; j++) {
            int cur = j & 1, nxt = cur ^ 1;
            if (j < 3) {
                uint32_t ja = aB + (j + 1) * 32, jb = bB + (j + 1) * 32;
                #pragma unroll
                for (int mt = 0; mt < 4; mt++)
                    ldsm_x4(ja + mt * 16 * LDAB, af[nxt][mt][0], af[nxt][mt][1],
                            af[nxt][mt][2], af[nxt][mt][3]);
                #pragma unroll
                for (int p = 0; p < 2; p++)
                    ldsm_x4(jb + p * 16 * LDAB, bf[nxt][p][0], bf[nxt][p][1],
                            bf[nxt][p][2], bf[nxt][p][3]);
            }
            #pragma unroll
            for (int mt = 0; mt < 4; mt++)
                #pragma unroll
                for (int nt = 0; nt < 4; nt++)
                    mma_bf16(acc[mt][nt], af[cur][mt],
                             bf[cur][nt >> 1][nt & 1], bf[cur][nt >> 1][(nt & 1) + 2]);
        }
    }

    int qrow = lane >> 2, qcol = (lane & 3) * 2;
    #pragma unroll
    for (int mt = 0; mt < 4; mt++) {
        #pragma unroll
        for (int half = 0; half < 2; half++) {
            int m = wm + mt * 16 + qrow + 8 * half;
            if (m >= rows) continue;
            size_t orow = (size_t)(p0 + m) * F_FF + c0;
            #pragma unroll
            for (int nt = 0; nt < 4; nt++) {
                int nl = wn + nt * 8 + qcol;
                float v0 = gelu_f(acc[mt][nt][2 * half]     + s_bias[nl]);
                float v1 = gelu_f(acc[mt][nt][2 * half + 1] + s_bias[nl + 1]);
                __nv_bfloat16 h0 = __float2bfloat16(v0), h1 = __float2bfloat16(v1);
                __nv_bfloat16 l0 = __float2bfloat16(v0 - __bfloat162float(h0));
                __nv_bfloat16 l1 = __float2bfloat16(v1 - __bfloat162float(h1));
                __nv_bfloat162 ph, pl;
                ph.x = h0; ph.y = h1; pl.x = l0; pl.y = l1;
                *(__nv_bfloat162*)(g_hid_hi + orow + nl) = ph;
                *(__nv_bfloat162*)(g_hid_lo + orow + nl) = pl;
            }
        }
    }
}

// GEMM2: y = hidden @ w2T^T + b2 (fp32 out)
__global__ __launch_bounds__(256, 2) void gemm2_mma(const float* __restrict__ b2) {
    int tile = blockIdx.x;
    int rows = g_tile_rows[tile];
    if (rows == 0) return;
    int e = g_tile_e[tile], p0 = g_tile_p0[tile];
    int c0 = blockIdx.y * BN;

    extern __shared__ char dyn[];
    float* s_bias = (float*)(dyn + SBIAS_OFF);

    int t = threadIdx.x, wid = t >> 5, lane = t & 31;
    if (t < BN) s_bias[t] = b2[(size_t)e * D_MODEL + c0 + t];
    __syncthreads();

    uint32_t sb = smem_u32(dyn);
    uint32_t sA[3] = {sb, sb + SA_ST, sb + 2 * SA_ST};
    uint32_t sB[3] = {sb + 3 * SA_ST, sb + 3 * SA_ST + SB_ST, sb + 3 * SA_ST + 2 * SB_ST};

    auto loadStage = [&](int kt, int st) {
        int seg = kt >> 5, kk = (kt & 31) * BK;
        const __nv_bfloat16* Ag = (seg < 2) ? g_hid_hi : g_hid_lo;
        const __nv_bfloat16* Bg = (seg == 1) ? g_w2T_lo : g_w2T_hi;
        const __nv_bfloat16* Abase = Ag + (size_t)p0 * F_FF + kk;
        const __nv_bfloat16* Bbase = Bg + ((size_t)e * D_MODEL + c0) * F_FF + kk;
        #pragma unroll
        for (int it = 0; it < 4; it++) {
            int idx = t + it * 256;
            int row = idx >> 3, c = idx & 7;
            CP_ASYNC16(sA[st] + row * LDAB + c * 16,
                       Abase + (size_t)row * F_FF + c * 8);
        }
        #pragma unroll
        for (int it = 0; it < 4; it++) {
            int idx = t + it * 256;
            int row = idx >> 3, c = idx & 7;
            CP_ASYNC16(sB[st] + row * LDAB + c * 16,
                       Bbase + (size_t)row * F_FF + c * 8);
        }
        CP_COMMIT();
    };

    int wm = (wid >> 2) * 64, wn = (wid & 3) * 32;
    uint32_t aOff = (uint32_t)((wm + (lane & 15)) * LDAB + (lane >> 4) * 16);
    uint32_t bOff = (uint32_t)((wn + (lane & 15)) * LDAB + (lane >> 4) * 16);

    float acc[4][4][4];
    #pragma unroll
    for (int i = 0; i < 4; i++)
        #pragma unroll
        for (int j = 0; j < 4; j++)
            #pragma unroll
            for (int r = 0; r < 4; r++) acc[i][j][r] = 0.0f;

    const int KT = (F_FF / BK) * 3;   // 96
    loadStage(0, 0);
    loadStage(1, 1);

    uint32_t af[2][4][4], bf[2][2][4];
    #pragma unroll 1
    for (int kt = 0; kt < KT; kt++) {
        if (kt + 1 < KT) { CP_WAIT1(); } else { CP_WAIT0(); }
        __syncthreads();
        if (kt + 2 < KT) loadStage(kt + 2, (kt + 2) % 3);
        int st = kt % 3;
        uint32_t aB = sA[st] + aOff, bB = sB[st] + bOff;

        #pragma unroll
        for (int mt = 0; mt < 4; mt++)
            ldsm_x4(aB + mt * 16 * LDAB, af[0][mt][0], af[0][mt][1], af[0][mt][2], af[0][mt][3]);
        #pragma unroll
        for (int p = 0; p < 2; p++)
            ldsm_x4(bB + p * 16 * LDAB, bf[0][p][0], bf[0][p][1], bf[0][p][2], bf[0][p][3]);

        #pragma unroll
        for (int j = 0; j < 4; j++) {
            int cur = j & 1, nxt = cur ^ 1;
            if (j < 3) {
                uint32_t ja = aB + (j + 1) * 32, jb = bB + (j + 1) * 32;
                #pragma unroll
                for (int mt = 0; mt < 4; mt++)
                    ldsm_x4(ja + mt * 16 * LDAB, af[nxt][mt][0], af[nxt][mt][1],
                            af[nxt][mt][2], af[nxt][mt][3]);
                #pragma unroll
                for (int p = 0; p < 2; p++)
                    ldsm_x4(jb + p * 16 * LDAB, bf[nxt][p][0], bf[nxt][p][1],
                            bf[nxt][p][2], bf[nxt][p][3]);
            }
            #pragma unroll
            for (int mt = 0; mt < 4; mt++)
                #pragma unroll
                for (int nt = 0; nt < 4; nt++)
                    mma_bf16(acc[mt][nt], af[cur][mt],
                             bf[cur][nt >> 1][nt & 1], bf[cur][nt >> 1][(nt & 1) + 2]);
        }
    }

    int qrow = lane >> 2, qcol = (lane & 3) * 2;
    #pragma unroll
    for (int mt = 0; mt < 4; mt++) {
        #pragma unroll
        for (int half = 0; half < 2; half++) {
            int m = wm + mt * 16 + qrow + 8 * half;
            if (m >= rows) continue;
            size_t orow = (size_t)(p0 + m) * D_MODEL + c0;
            #pragma unroll
            for (int nt = 0; nt < 4; nt++) {
                int nl = wn + nt * 8 + qcol;
                float2 v;
                v.x = acc[mt][nt][2 * half]     + s_bias[nl];
                v.y = acc[mt][nt][2 * half + 1] + s_bias[nl + 1];
                *(float2*)(g_y + orow + nl) = v;
            }
        }
    }
}

// ---------------- combine ----------------
__global__ __launch_bounds__(128) void combine_kernel(float* __restrict__ out) {
    int n = blockIdx.x;
    int pa = g_pos[2 * n], pb = g_pos[2 * n + 1];
    float w0 = g_topk_w[2 * n], w1 = g_topk_w[2 * n + 1];
    int d = threadIdx.x * 4;
    float4 y0 = *(const float4*)(g_y + (size_t)pa * D_MODEL + d);
    float4 y1 = *(const float4*)(g_y + (size_t)pb * D_MODEL + d);
    float4 r;
    r.x = w0 * y0.x + w1 * y1.x;
    r.y = w0 * y0.y + w1 * y1.y;
    r.z = w0 * y0.z + w1 * y1.z;
    r.w = w0 * y0.w + w1 * y1.w;
    *(float4*)(out + (size_t)n * D_MODEL + d) = r;
}

// ---------------- launch ----------------
extern "C" void kernel_launch(void* const* d_in, const int* in_sizes, int n_in,
                              void* d_out, int out_size) {
    const float* h_t    = (const float*)d_in[0];
    const float* gate_w = (const float*)d_in[1];
    const float* w1     = (const float*)d_in[2];
    const float* b1     = (const float*)d_in[3];
    const float* w2     = (const float*)d_in[4];
    const float* b2     = (const float*)d_in[5];
    float* out = (float*)d_out;

    cudaFuncSetAttribute(gemm1_mma, cudaFuncAttributeMaxDynamicSharedMemorySize, SMEM_BYTES);
    cudaFuncSetAttribute(gemm2_mma, cudaFuncAttributeMaxDynamicSharedMemorySize, SMEM_BYTES);

    init_kernel<<<1, 32>>>();
    prep_kernel<<<NB_GATE + NB_W1T + NB_W2T, 256>>>(h_t, gate_w, w1, w2, out);
    finalize_kernel<<<1, 32>>>(out);
    scatter_kernel<<<N_TOK / 256, 256>>>();
    gemm1_mma<<<dim3(NT_TILES, F_FF / BN), 256, SMEM_BYTES>>>(b1);   // ncu slot
    gemm2_mma<<<dim3(NT_TILES, D_MODEL / BN), 256, SMEM_BYTES>>>(b2);
    combine_kernel<<<N_TOK, 128>>>(out);
}

// round 9
// speedup vs baseline: 2.4489x; 1.0415x over previous
#include <cuda_runtime.h>
#include <cuda_bf16.h>
#include <math.h>
#include <stdint.h>

#define D_MODEL 512
#define F_FF    2048
#define N_EXP   8
#define N_TOK   8192
#define N_ASSIGN (N_TOK * 2)
#define NT_TILES 160
#define BM 128
#define BN 128
#define BK 32            // K elems per stage (each row carries hi+lo limbs)
#define LDAB 144         // smem row: 64B hi | 64B lo | 16B pad

#define SA_ST (BM * LDAB)                 // 18432
#define STOK_OFF  (6 * SA_ST)             // 110592 (3 A stages + 3 B stages)
#define SBIAS_OFF (STOK_OFF + 512)
#define SMEM_BYTES (SBIAS_OFF + 512)      // 111616

// prep block partition
#define NB_GATE 1024
#define NB_W1T  8192
#define NB_W2T  8192

#define OUT_LOGITS ((size_t)N_TOK * D_MODEL)
#define OUT_PROBS  (OUT_LOGITS + (size_t)N_TOK * N_EXP)
#define OUT_Z      (OUT_PROBS + (size_t)N_TOK * N_EXP)
#define OUT_LB     (OUT_Z + 1)
#define OUT_LOAD   (OUT_LB + 1)
#define OUT_CNT    (OUT_LOAD + N_EXP)

// ---------------- static scratch ----------------
__device__ __nv_bfloat16 g_tok_hi[N_TOK * D_MODEL];
__device__ __nv_bfloat16 g_tok_lo[N_TOK * D_MODEL];
__device__ __nv_bfloat16 g_w1T_hi[N_EXP * F_FF * D_MODEL];   // [E, F, D] K-major
__device__ __nv_bfloat16 g_w1T_lo[N_EXP * F_FF * D_MODEL];
__device__ __nv_bfloat16 g_w2T_hi[N_EXP * D_MODEL * F_FF];   // [E, D, F] K-major
__device__ __nv_bfloat16 g_w2T_lo[N_EXP * D_MODEL * F_FF];
__device__ __nv_bfloat16 g_hid_hi[(N_ASSIGN + BM) * F_FF];
__device__ __nv_bfloat16 g_hid_lo[(N_ASSIGN + BM) * F_FF];
__device__ float g_y[(size_t)(N_ASSIGN + BM) * D_MODEL];
__device__ int   g_tok[N_ASSIGN + BM];
__device__ int   g_pos[N_ASSIGN];
__device__ int   g_topk_idx[N_ASSIGN];
__device__ float g_topk_w[N_ASSIGN];
__device__ int   g_cnt[N_EXP];
__device__ int   g_cursor[N_EXP];
__device__ float g_zsum;
__device__ float g_loadsum[N_EXP];
__device__ int   g_tile_e[NT_TILES];
__device__ int   g_tile_p0[NT_TILES];
__device__ int   g_tile_rows[NT_TILES];

// ---------------- PTX helpers (baseline ISA only) ----------------
__device__ __forceinline__ uint32_t smem_u32(const void* p) {
    uint32_t a;
    asm("{ .reg .u64 t; cvta.to.shared.u64 t, %1; cvt.u32.u64 %0, t; }" : "=r"(a) : "l"(p));
    return a;
}
#define CP_ASYNC16(dst, src) \
    asm volatile("cp.async.cg.shared.global [%0], [%1], 16;" :: "r"(dst), "l"(src) : "memory")
#define CP_COMMIT() asm volatile("cp.async.commit_group;" ::: "memory")
#define CP_WAIT1()  asm volatile("cp.async.wait_group 1;" ::: "memory")
#define CP_WAIT0()  asm volatile("cp.async.wait_group 0;" ::: "memory")

__device__ __forceinline__ void ldsm_x4(uint32_t addr, uint32_t& r0, uint32_t& r1,
                                        uint32_t& r2, uint32_t& r3) {
    asm volatile("ldmatrix.sync.aligned.m8n8.x4.shared.b16 {%0,%1,%2,%3}, [%4];"
        : "=r"(r0), "=r"(r1), "=r"(r2), "=r"(r3) : "r"(addr));
}
__device__ __forceinline__ void mma_bf16(float* d, const uint32_t* a,
                                         uint32_t b0, uint32_t b1) {
    asm volatile(
        "mma.sync.aligned.m16n8k16.row.col.f32.bf16.bf16.f32 "
        "{%0,%1,%2,%3}, {%4,%5,%6,%7}, {%8,%9}, {%0,%1,%2,%3};"
        : "+f"(d[0]), "+f"(d[1]), "+f"(d[2]), "+f"(d[3])
        : "r"(a[0]), "r"(a[1]), "r"(a[2]), "r"(a[3]), "r"(b0), "r"(b1));
}
__device__ __forceinline__ float gelu_f(float x) {
    const float c = 0.7978845608028654f;
    float x3 = x * x * x;
    return 0.5f * x * (1.0f + tanhf(c * (x + 0.044715f * x3)));
}

// ---------------- init ----------------
__global__ void init_kernel() {
    int t = threadIdx.x;
    if (t < N_EXP) { g_cnt[t] = 0; g_loadsum[t] = 0.0f; }
    if (t == 0) g_zsum = 0.0f;
}

// ================ prep: gating(+stats) + token split + weight transposes ================
__device__ __forceinline__ void transpose_split_part(
    float (*tile)[33], const float* __restrict__ in,
    __nv_bfloat16* __restrict__ out_hi, __nv_bfloat16* __restrict__ out_lo,
    int R, int C, int e, int c0, int r0, int tx, int ty)
{
    const float* src = in + (size_t)e * R * C;
    #pragma unroll
    for (int i = ty; i < 32; i += 8)
        tile[i][tx] = src[(size_t)(r0 + i) * C + c0 + tx];
    __syncthreads();
    __nv_bfloat16* dh = out_hi + (size_t)e * R * C;
    __nv_bfloat16* dl = out_lo + (size_t)e * R * C;
    #pragma unroll
    for (int i = ty; i < 32; i += 8) {
        float v = tile[tx][i];
        __nv_bfloat16 h = __float2bfloat16(v);
        __nv_bfloat16 l = __float2bfloat16(v - __bfloat162float(h));
        dh[(size_t)(c0 + i) * R + r0 + tx] = h;
        dl[(size_t)(c0 + i) * R + r0 + tx] = l;
    }
}

__global__ __launch_bounds__(256) void prep_kernel(
    const float* __restrict__ tokens, const float* __restrict__ gate_w,
    const float* __restrict__ w1, const float* __restrict__ w2,
    float* __restrict__ out)
{
    __shared__ __align__(16) char sbuf[16384];
    __shared__ float s_load[N_EXP];
    __shared__ int   s_cnt[N_EXP];
    __shared__ float s_z;
    int b = blockIdx.x;
    int t = threadIdx.x;

    if (b >= NB_GATE) {
        float (*tile)[33] = (float(*)[33])sbuf;
        int tx = t & 31, ty = t >> 5;
        if (b < NB_GATE + NB_W1T) {
            int idx = b - NB_GATE;
            int e = idx >> 10, rem = idx & 1023;
            int c0 = (rem & 63) * 32, r0 = (rem >> 6) * 32;
            transpose_split_part(tile, w1, g_w1T_hi, g_w1T_lo, D_MODEL, F_FF, e, c0, r0, tx, ty);
        } else {
            int idx = b - NB_GATE - NB_W1T;
            int e = idx >> 10, rem = idx & 1023;
            int c0 = (rem & 15) * 32, r0 = (rem >> 4) * 32;
            transpose_split_part(tile, w2, g_w2T_hi, g_w2T_lo, F_FF, D_MODEL, e, c0, r0, tx, ty);
        }
        return;
    }

    float* gwT = (float*)sbuf;   // [8][512]
    for (int i = t; i < D_MODEL * N_EXP; i += 256) {
        int d = i >> 3, e = i & 7;
        gwT[e * 512 + d] = gate_w[i];
    }
    if (t < N_EXP) { s_load[t] = 0.0f; s_cnt[t] = 0; }
    if (t == 0) s_z = 0.0f;
    __syncthreads();

    int n0 = b * 8;
    {
        const float4* src = (const float4*)(tokens + (size_t)n0 * D_MODEL);
        size_t obase = (size_t)n0 * D_MODEL;
        for (int i = t; i < 1024; i += 256) {
            float4 v = src[i];
            __nv_bfloat16 h0 = __float2bfloat16(v.x), h1 = __float2bfloat16(v.y);
            __nv_bfloat16 h2 = __float2bfloat16(v.z), h3 = __float2bfloat16(v.w);
            __nv_bfloat16 l0 = __float2bfloat16(v.x - __bfloat162float(h0));
            __nv_bfloat16 l1 = __float2bfloat16(v.y - __bfloat162float(h1));
            __nv_bfloat16 l2 = __float2bfloat16(v.z - __bfloat162float(h2));
            __nv_bfloat16 l3 = __float2bfloat16(v.w - __bfloat162float(h3));
            __nv_bfloat162 ph0, ph1, pl0, pl1;
            ph0.x = h0; ph0.y = h1; ph1.x = h2; ph1.y = h3;
            pl0.x = l0; pl0.y = l1; pl1.x = l2; pl1.y = l3;
            ((__nv_bfloat162*)(g_tok_hi + obase))[2*i]   = ph0;
            ((__nv_bfloat162*)(g_tok_hi + obase))[2*i+1] = ph1;
            ((__nv_bfloat162*)(g_tok_lo + obase))[2*i]   = pl0;
            ((__nv_bfloat162*)(g_tok_lo + obase))[2*i+1] = pl1;
        }
    }

    int warp = t >> 5, lane = t & 31;
    int n = n0 + warp;
    const float* x = tokens + (size_t)n * D_MODEL;

    float acc[8] = {0.f,0.f,0.f,0.f,0.f,0.f,0.f,0.f};
    for (int d = lane; d < D_MODEL; d += 32) {
        float xv = x[d];
        #pragma unroll
        for (int e = 0; e < 8; e++) acc[e] = fmaf(xv, gwT[e * 512 + d], acc[e]);
    }
    #pragma unroll
    for (int e = 0; e < 8; e++) {
        #pragma unroll
        for (int o = 16; o; o >>= 1)
            acc[e] += __shfl_down_sync(0xffffffffu, acc[e], o);
    }

    if (lane == 0) {
        float m = acc[0];
        #pragma unroll
        for (int e = 1; e < 8; e++) m = fmaxf(m, acc[e]);
        float p[8], s = 0.0f;
        #pragma unroll
        for (int e = 0; e < 8; e++) { p[e] = expf(acc[e] - m); s += p[e]; }
        float inv = 1.0f / s;
        #pragma unroll
        for (int e = 0; e < 8; e++) p[e] *= inv;

        float* gl = out + OUT_LOGITS + (size_t)n * N_EXP;
        float* pr = out + OUT_PROBS  + (size_t)n * N_EXP;
        #pragma unroll
        for (int e = 0; e < 8; e++) { gl[e] = acc[e]; pr[e] = p[e]; }

        float lse = m + logf(s);
        atomicAdd(&s_z, lse * lse);
        #pragma unroll
        for (int e = 0; e < 8; e++) atomicAdd(&s_load[e], p[e]);

        int i0 = 0; float m0 = p[0];
        #pragma unroll
        for (int e = 1; e < 8; e++) if (p[e] > m0) { m0 = p[e]; i0 = e; }
        int i1 = (i0 == 0) ? 1 : 0; float m1 = p[i1];
        #pragma unroll
        for (int e = 0; e < 8; e++)
            if (e != i0 && p[e] > m1) { m1 = p[e]; i1 = e; }
        float ws = m0 + m1;
        g_topk_idx[2 * n]     = i0;
        g_topk_idx[2 * n + 1] = i1;
        g_topk_w[2 * n]       = m0 / ws;
        g_topk_w[2 * n + 1]   = m1 / ws;
        atomicAdd(&s_cnt[i0], 1);
        atomicAdd(&s_cnt[i1], 1);
    }
    __syncthreads();
    if (t < N_EXP) {
        atomicAdd(&g_cnt[t], s_cnt[t]);
        atomicAdd(&g_loadsum[t], s_load[t]);
    }
    if (t == 0) atomicAdd(&g_zsum, s_z);
}

// ---------------- finalize ----------------
__global__ void finalize_kernel(float* __restrict__ out) {
    if (threadIdx.x != 0) return;
    int off = 0;
    float lb = 0.0f;
    int tcount = 0;
    for (int e = 0; e < N_EXP; e++) {
        g_cursor[e] = off;
        int cnt = g_cnt[e];
        float load = g_loadsum[e] / (float)N_TOK;
        out[OUT_LOAD + e] = load;
        out[OUT_CNT + e]  = (float)cnt;
        lb += ((float)cnt / (float)N_ASSIGN) * load;
        for (int r = 0; r < cnt; r += BM) {
            g_tile_e[tcount]    = e;
            g_tile_p0[tcount]   = off + r;
            int rem = cnt - r;
            g_tile_rows[tcount] = rem < BM ? rem : BM;
            tcount++;
        }
        off += cnt;
    }
    for (int i = tcount; i < NT_TILES; i++) g_tile_rows[i] = 0;
    out[OUT_LB] = (float)N_EXP * lb;
    out[OUT_Z]  = g_zsum / (float)N_TOK;
}

// ---------------- scatter ----------------
__global__ void scatter_kernel() {
    int n = blockIdx.x * blockDim.x + threadIdx.x;
    if (n >= N_TOK) return;
    #pragma unroll
    for (int k = 0; k < 2; k++) {
        int e = g_topk_idx[2 * n + k];
        int pos = atomicAdd(&g_cursor[e], 1);
        g_tok[pos] = n;
        g_pos[2 * n + k] = pos;
    }
}

// =============== fused-limb warp-MMA GEMMs ===============
// CTA 128x128, 8 warps 2(M)x4(N), warp tile 64x32. BK=32 per stage; each smem row
// holds hi(64B)|lo(64B)|pad(16B). Per k16: ldsm Ah/Al/Bh/Bl, then 3 MMA combos.

// GEMM1: hidden = gelu(gather(tokens) @ w1T^T + b1) -> split bf16 hi/lo
__global__ __launch_bounds__(256, 2) void gemm1_mma(const float* __restrict__ b1) {
    int tile = blockIdx.x;
    int rows = g_tile_rows[tile];
    if (rows == 0) return;
    int e = g_tile_e[tile], p0 = g_tile_p0[tile];
    int c0 = blockIdx.y * BN;

    extern __shared__ char dyn[];
    int*   s_tok  = (int*)(dyn + STOK_OFF);
    float* s_bias = (float*)(dyn + SBIAS_OFF);

    int t = threadIdx.x, wid = t >> 5, lane = t & 31;
    if (t < BM) {
        int rr = (t < rows) ? t : (rows - 1);
        s_tok[t]  = g_tok[p0 + rr];
        s_bias[t] = b1[(size_t)e * F_FF + c0 + t];
    }
    __syncthreads();

    uint32_t sb = smem_u32(dyn);
    uint32_t sA[3] = {sb, sb + SA_ST, sb + 2 * SA_ST};
    uint32_t sB[3] = {sb + 3 * SA_ST, sb + 4 * SA_ST, sb + 5 * SA_ST};

    auto loadStage = [&](int kt, int st) {
        int kk = kt * BK;
        // A: 128 rows x 8 chunks (4 hi + 4 lo)
        #pragma unroll
        for (int it = 0; it < 4; it++) {
            int idx = t + it * 256;
            int row = idx >> 3, c = idx & 7;
            const __nv_bfloat16* src = (c < 4)
                ? g_tok_hi + (size_t)s_tok[row] * D_MODEL + kk + c * 8
                : g_tok_lo + (size_t)s_tok[row] * D_MODEL + kk + (c - 4) * 8;
            CP_ASYNC16(sA[st] + row * LDAB + ((c < 4) ? c * 16 : 64 + (c - 4) * 16), src);
        }
        const __nv_bfloat16* Bh = g_w1T_hi + ((size_t)e * F_FF + c0) * D_MODEL + kk;
        const __nv_bfloat16* Bl = g_w1T_lo + ((size_t)e * F_FF + c0) * D_MODEL + kk;
        #pragma unroll
        for (int it = 0; it < 4; it++) {
            int idx = t + it * 256;
            int row = idx >> 3, c = idx & 7;
            const __nv_bfloat16* src = (c < 4)
                ? Bh + (size_t)row * D_MODEL + c * 8
                : Bl + (size_t)row * D_MODEL + (c - 4) * 8;
            CP_ASYNC16(sB[st] + row * LDAB + ((c < 4) ? c * 16 : 64 + (c - 4) * 16), src);
        }
        CP_COMMIT();
    };

    int wm = (wid >> 2) * 64, wn = (wid & 3) * 32;
    uint32_t aOff = (uint32_t)((wm + (lane & 15)) * LDAB + (lane >> 4) * 16);
    uint32_t bOff = (uint32_t)((wn + (lane & 15)) * LDAB + (lane >> 4) * 16);

    float acc[4][4][4];
    #pragma unroll
    for (int i = 0; i < 4; i++)
        #pragma unroll
        for (int j = 0; j < 4; j++)
            #pragma unroll
            for (int r = 0; r < 4; r++) acc[i][j][r] = 0.0f;

    const int KT = D_MODEL / BK;   // 16
    loadStage(0, 0);
    loadStage(1, 1);
    #pragma unroll 1
    for (int kt = 0; kt < KT; kt++) {
        if (kt + 1 < KT) { CP_WAIT1(); } else { CP_WAIT0(); }
        __syncthreads();
        if (kt + 2 < KT) loadStage(kt + 2, (kt + 2) % 3);
        int st = kt % 3;
        uint32_t aB = sA[st] + aOff, bB = sB[st] + bOff;

        #pragma unroll
        for (int j = 0; j < 2; j++) {          // k16 sub-chunks
            uint32_t ah[4][4], al[4][4], bh[2][4], bl[2][4];
            #pragma unroll
            for (int mt = 0; mt < 4; mt++) {
                ldsm_x4(aB + mt * 16 * LDAB + j * 32,
                        ah[mt][0], ah[mt][1], ah[mt][2], ah[mt][3]);
                ldsm_x4(aB + mt * 16 * LDAB + 64 + j * 32,
                        al[mt][0], al[mt][1], al[mt][2], al[mt][3]);
            }
            #pragma unroll
            for (int p = 0; p < 2; p++) {
                ldsm_x4(bB + p * 16 * LDAB + j * 32,
                        bh[p][0], bh[p][1], bh[p][2], bh[p][3]);
                ldsm_x4(bB + p * 16 * LDAB + 64 + j * 32,
                        bl[p][0], bl[p][1], bl[p][2], bl[p][3]);
            }
            // combo 0: Ah * Bh
            #pragma unroll
            for (int mt = 0; mt < 4; mt++)
                #pragma unroll
                for (int nt = 0; nt < 4; nt++)
                    mma_bf16(acc[mt][nt], ah[mt], bh[nt >> 1][nt & 1], bh[nt >> 1][(nt & 1) + 2]);
            // combo 1: Ah * Bl
            #pragma unroll
            for (int mt = 0; mt < 4; mt++)
                #pragma unroll
                for (int nt = 0; nt < 4; nt++)
                    mma_bf16(acc[mt][nt], ah[mt], bl[nt >> 1][nt & 1], bl[nt >> 1][(nt & 1) + 2]);
            // combo 2: Al * Bh
            #pragma unroll
            for (int mt = 0; mt < 4; mt++)
                #pragma unroll
                for (int nt = 0; nt < 4; nt++)
                    mma_bf16(acc[mt][nt], al[mt], bh[nt >> 1][nt & 1], bh[nt >> 1][(nt & 1) + 2]);
        }
    }

    int qrow = lane >> 2, qcol = (lane & 3) * 2;
    #pragma unroll
    for (int mt = 0; mt < 4; mt++) {
        #pragma unroll
        for (int half = 0; half < 2; half++) {
            int m = wm + mt * 16 + qrow + 8 * half;
            if (m >= rows) continue;
            size_t orow = (size_t)(p0 + m) * F_FF + c0;
            #pragma unroll
            for (int nt = 0; nt < 4; nt++) {
                int nl = wn + nt * 8 + qcol;
                float v0 = gelu_f(acc[mt][nt][2 * half]     + s_bias[nl]);
                float v1 = gelu_f(acc[mt][nt][2 * half + 1] + s_bias[nl + 1]);
                __nv_bfloat16 h0 = __float2bfloat16(v0), h1 = __float2bfloat16(v1);
                __nv_bfloat16 l0 = __float2bfloat16(v0 - __bfloat162float(h0));
                __nv_bfloat16 l1 = __float2bfloat16(v1 - __bfloat162float(h1));
                __nv_bfloat162 ph, pl;
                ph.x = h0; ph.y = h1; pl.x = l0; pl.y = l1;
                *(__nv_bfloat162*)(g_hid_hi + orow + nl) = ph;
                *(__nv_bfloat162*)(g_hid_lo + orow + nl) = pl;
            }
        }
    }
}

// GEMM2: y = hidden @ w2T^^T + b2 (fp32 out)
__global__ __launch_bounds__(256, 2) void gemm2_mma(const float* __restrict__ b2) {
    int tile = blockIdx.x;
    int rows = g_tile_rows[tile];
    if (rows == 0) return;
    int e = g_tile_e[tile], p0 = g_tile_p0[tile];
    int c0 = blockIdx.y * BN;

    extern __shared__ char dyn[];
    float* s_bias = (float*)(dyn + SBIAS_OFF);

    int t = threadIdx.x, wid = t >> 5, lane = t & 31;
    if (t < BN) s_bias[t] = b2[(size_t)e * D_MODEL + c0 + t];
    __syncthreads();

    uint32_t sb = smem_u32(dyn);
    uint32_t sA[3] = {sb, sb + SA_ST, sb + 2 * SA_ST};
    uint32_t sB[3] = {sb + 3 * SA_ST, sb + 4 * SA_ST, sb + 5 * SA_ST};

    auto loadStage = [&](int kt, int st) {
        int kk = kt * BK;
        const __nv_bfloat16* Ah = g_hid_hi + (size_t)p0 * F_FF + kk;
        const __nv_bfloat16* Al = g_hid_lo + (size_t)p0 * F_FF + kk;
        const __nv_bfloat16* Bh = g_w2T_hi + ((size_t)e * D_MODEL + c0) * F_FF + kk;
        const __nv_bfloat16* Bl = g_w2T_lo + ((size_t)e * D_MODEL + c0) * F_FF + kk;
        #pragma unroll
        for (int it = 0; it < 4; it++) {
            int idx = t + it * 256;
            int row = idx >> 3, c = idx & 7;
            const __nv_bfloat16* src = (c < 4)
                ? Ah + (size_t)row * F_FF + c * 8
                : Al + (size_t)row * F_FF + (c - 4) * 8;
            CP_ASYNC16(sA[st] + row * LDAB + ((c < 4) ? c * 16 : 64 + (c - 4) * 16), src);
        }
        #pragma unroll
        for (int it = 0; it < 4; it++) {
            int idx = t + it * 256;
            int row = idx >> 3, c = idx & 7;
            const __nv_bfloat16* src = (c < 4)
                ? Bh + (size_t)row * F_FF + c * 8
                : Bl + (size_t)row * F_FF + (c - 4) * 8;
            CP_ASYNC16(sB[st] + row * LDAB + ((c < 4) ? c * 16 : 64 + (c - 4) * 16), src);
        }
        CP_COMMIT();
    };

    int wm = (wid >> 2) * 64, wn = (wid & 3) * 32;
    uint32_t aOff = (uint32_t)((wm + (lane & 15)) * LDAB + (lane >> 4) * 16);
    uint32_t bOff = (uint32_t)((wn + (lane & 15)) * LDAB + (lane >> 4) * 16);

    float acc[4][4][4];
    #pragma unroll
    for (int i = 0; i < 4; i++)
        #pragma unroll
        for (int j = 0; j < 4; j++)
            #pragma unroll
            for (int r = 0; r < 4; r++) acc[i][j][r] = 0.0f;

    const int KT = F_FF / BK;   // 64
    loadStage(0, 0);
    loadStage(1, 1);
    #pragma unroll 1
    for (int kt = 0; kt < KT; kt++) {
        if (kt + 1 < KT) { CP_WAIT1(); } else { CP_WAIT0(); }
        __syncthreads();
        if (kt + 2 < KT) loadStage(kt + 2, (kt + 2) % 3);
        int st = kt % 3;
        uint32_t aB = sA[st] + aOff, bB = sB[st] + bOff;

        #pragma unroll
        for (int j = 0; j < 2; j++) {
            uint32_t ah[4][4], al[4][4], bh[2][4], bl[2][4];
            #pragma unroll
            for (int mt = 0; mt < 4; mt++) {
                ldsm_x4(aB + mt * 16 * LDAB + j * 32,
                        ah[mt][0], ah[mt][1], ah[mt][2], ah[mt][3]);
                ldsm_x4(aB + mt * 16 * LDAB + 64 + j * 32,
                        al[mt][0], al[mt][1], al[mt][2], al[mt][3]);
            }
            #pragma unroll
            for (int p = 0; p < 2; p++) {
                ldsm_x4(bB + p * 16 * LDAB + j * 32,
                        bh[p][0], bh[p][1], bh[p][2], bh[p][3]);
                ldsm_x4(bB + p * 16 * LDAB + 64 + j * 32,
                        bl[p][0], bl[p][1], bl[p][2], bl[p][3]);
            }
            #pragma unroll
            for (int mt = 0; mt < 4; mt++)
                #pragma unroll
                for (int nt = 0; nt < 4; nt++)
                    mma_bf16(acc[mt][nt], ah[mt], bh[nt >> 1][nt & 1], bh[nt >> 1][(nt & 1) + 2]);
            #pragma unroll
            for (int mt = 0; mt < 4; mt++)
                #pragma unroll
                for (int nt = 0; nt < 4; nt++)
                    mma_bf16(acc[mt][nt], ah[mt], bl[nt >> 1][nt & 1], bl[nt >> 1][(nt & 1) + 2]);
            #pragma unroll
            for (int mt = 0; mt < 4; mt++)
                #pragma unroll
                for (int nt = 0; nt < 4; nt++)
                    mma_bf16(acc[mt][nt], al[mt], bh[nt >> 1][nt & 1], bh[nt >> 1][(nt & 1) + 2]);
        }
    }

    int qrow = lane >> 2, qcol = (lane & 3) * 2;
    #pragma unroll
    for (int mt = 0; mt < 4; mt++) {
        #pragma unroll
        for (int half = 0; half < 2; half++) {
            int m = wm + mt * 16 + qrow + 8 * half;
            if (m >= rows) continue;
            size_t orow = (size_t)(p0 + m) * D_MODEL + c0;
            #pragma unroll
            for (int nt = 0; nt < 4; nt++) {
                int nl = wn + nt * 8 + qcol;
                float2 v;
                v.x = acc[mt][nt][2 * half]     + s_bias[nl];
                v.y = acc[mt][nt][2 * half + 1] + s_bias[nl + 1];
                *(float2*)(g_y + orow + nl) = v;
            }
        }
    }
}

// ---------------- combine ----------------
__global__ __launch_bounds__(128) void combine_kernel(float* __restrict__ out) {
    int n = blockIdx.x;
    int pa = g_pos[2 * n], pb = g_pos[2 * n + 1];
    float w0 = g_topk_w[2 * n], w1 = g_topk_w[2 * n + 1];
    int d = threadIdx.x * 4;
    float4 y0 = *(const float4*)(g_y + (size_t)pa * D_MODEL + d);
    float4 y1 = *(const float4*)(g_y + (size_t)pb * D_MODEL + d);
    float4 r;
    r.x = w0 * y0.x + w1 * y1.x;
    r.y = w0 * y0.y + w1 * y1.y;
    r.z = w0 * y0.z + w1 * y1.z;
    r.w = w0 * y0.w + w1 * y1.w;
    *(float4*)(out + (size_t)n * D_MODEL + d) = r;
}

// ---------------- launch ----------------
extern "C" void kernel_launch(void* const* d_in, const int* in_sizes, int n_in,
                              void* d_out, int out_size) {
    const float* h_t    = (const float*)d_in[0];
    const float* gate_w = (const float*)d_in[1];
    const float* w1     = (const float*)d_in[2];
    const float* b1     = (const float*)d_in[3];
    const float* w2     = (const float*)d_in[4];
    const float* b2     = (const float*)d_in[5];
    float* out = (float*)d_out;

    cudaFuncSetAttribute(gemm1_mma, cudaFuncAttributeMaxDynamicSharedMemorySize, SMEM_BYTES);
    cudaFuncSetAttribute(gemm2_mma, cudaFuncAttributeMaxDynamicSharedMemorySize, SMEM_BYTES);

    init_kernel<<<1, 32>>>();
    prep_kernel<<<NB_GATE + NB_W1T + NB_W2T, 256>>>(h_t, gate_w, w1, w2, out);
    finalize_kernel<<<1, 32>>>(out);
    scatter_kernel<<<N_TOK / 256, 256>>>();
    gemm1_mma<<<dim3(NT_TILES, F_FF / BN), 256, SMEM_BYTES>>>(b1);
    gemm2_mma<<<dim3(NT_TILES, D_MODEL / BN), 256, SMEM_BYTES>>>(b2);
    combine_kernel<<<N_TOK, 128>>>(out);
}

// round 10
// speedup vs baseline: 2.5718x; 1.0502x over previous
#include <cuda_runtime.h>
#include <cuda_bf16.h>
#include <math.h>
#include <stdint.h>

#define D_MODEL 512
#define F_FF    2048
#define N_EXP   8
#define N_TOK   8192
#define N_ASSIGN (N_TOK * 2)
#define NT_TILES 160
#define BM 128
#define BN 128
#define BK 32            // K elems per stage (each row carries hi+lo limbs)
#define LDAB 144         // smem row: 64B hi | 64B lo | 16B pad

#define SA_ST (BM * LDAB)                 // 18432
#define STOK_OFF  (6 * SA_ST)             // 110592 (3 A stages + 3 B stages)
#define SBIAS_OFF (STOK_OFF + 512)
#define SMEM_BYTES (SBIAS_OFF + 512)      // 111616

// prep block partition
#define NB_GATE 1024
#define NB_W1T  8192
#define NB_W2T  8192

#define OUT_LOGITS ((size_t)N_TOK * D_MODEL)
#define OUT_PROBS  (OUT_LOGITS + (size_t)N_TOK * N_EXP)
#define OUT_Z      (OUT_PROBS + (size_t)N_TOK * N_EXP)
#define OUT_LB     (OUT_Z + 1)
#define OUT_LOAD   (OUT_LB + 1)
#define OUT_CNT    (OUT_LOAD + N_EXP)

// ---------------- static scratch ----------------
__device__ __nv_bfloat16 g_tok_hi[N_TOK * D_MODEL];
__device__ __nv_bfloat16 g_tok_lo[N_TOK * D_MODEL];
__device__ __nv_bfloat16 g_w1T_hi[N_EXP * F_FF * D_MODEL];   // [E, F, D] K-major
__device__ __nv_bfloat16 g_w1T_lo[N_EXP * F_FF * D_MODEL];
__device__ __nv_bfloat16 g_w2T_hi[N_EXP * D_MODEL * F_FF];   // [E, D, F] K-major
__device__ __nv_bfloat16 g_w2T_lo[N_EXP * D_MODEL * F_FF];
__device__ __nv_bfloat16 g_hid_hi[(N_ASSIGN + BM) * F_FF];
__device__ __nv_bfloat16 g_hid_lo[(N_ASSIGN + BM) * F_FF];
__device__ float g_y [(size_t)(N_ASSIGN + BM) * D_MODEL];
__device__ float g_y2[(size_t)(N_ASSIGN + BM) * D_MODEL];
__device__ int   g_tok[N_ASSIGN + BM];
__device__ int   g_pos[N_ASSIGN];
__device__ int   g_topk_idx[N_ASSIGN];
__device__ float g_topk_w[N_ASSIGN];
__device__ int   g_cnt[N_EXP];
__device__ int   g_cursor[N_EXP];
__device__ float g_zsum;
__device__ float g_loadsum[N_EXP];
__device__ int   g_tile_e[NT_TILES];
__device__ int   g_tile_p0[NT_TILES];
__device__ int   g_tile_rows[NT_TILES];

// ---------------- PTX helpers (baseline ISA only) ----------------
__device__ __forceinline__ uint32_t smem_u32(const void* p) {
    uint32_t a;
    asm("{ .reg .u64 t; cvta.to.shared.u64 t, %1; cvt.u32.u64 %0, t; }" : "=r"(a) : "l"(p));
    return a;
}
#define CP_ASYNC16(dst, src) \
    asm volatile("cp.async.cg.shared.global [%0], [%1], 16;" :: "r"(dst), "l"(src) : "memory")
#define CP_COMMIT() asm volatile("cp.async.commit_group;" ::: "memory")
#define CP_WAIT1()  asm volatile("cp.async.wait_group 1;" ::: "memory")
#define CP_WAIT0()  asm volatile("cp.async.wait_group 0;" ::: "memory")

__device__ __forceinline__ void ldsm_x4(uint32_t addr, uint32_t& r0, uint32_t& r1,
                                        uint32_t& r2, uint32_t& r3) {
    asm volatile("ldmatrix.sync.aligned.m8n8.x4.shared.b16 {%0,%1,%2,%3}, [%4];"
        : "=r"(r0), "=r"(r1), "=r"(r2), "=r"(r3) : "r"(addr));
}
__device__ __forceinline__ void mma_bf16(float* d, const uint32_t* a,
                                         uint32_t b0, uint32_t b1) {
    asm volatile(
        "mma.sync.aligned.m16n8k16.row.col.f32.bf16.bf16.f32 "
        "{%0,%1,%2,%3}, {%4,%5,%6,%7}, {%8,%9}, {%0,%1,%2,%3};"
        : "+f"(d[0]), "+f"(d[1]), "+f"(d[2]), "+f"(d[3])
        : "r"(a[0]), "r"(a[1]), "r"(a[2]), "r"(a[3]), "r"(b0), "r"(b1));
}
__device__ __forceinline__ float gelu_f(float x) {
    const float c = 0.7978845608028654f;
    float x3 = x * x * x;
    return 0.5f * x * (1.0f + tanhf(c * (x + 0.044715f * x3)));
}

// ---------------- init ----------------
__global__ void init_kernel() {
    int t = threadIdx.x;
    if (t < N_EXP) { g_cnt[t] = 0; g_loadsum[t] = 0.0f; }
    if (t == 0) g_zsum = 0.0f;
}

// ================ prep: gating(+stats) + token split + weight transposes ================
__device__ __forceinline__ void transpose_split_part(
    float (*tile)[33], const float* __restrict__ in,
    __nv_bfloat16* __restrict__ out_hi, __nv_bfloat16* __restrict__ out_lo,
    int R, int C, int e, int c0, int r0, int tx, int ty)
{
    const float* src = in + (size_t)e * R * C;
    #pragma unroll
    for (int i = ty; i < 32; i += 8)
        tile[i][tx] = src[(size_t)(r0 + i) * C + c0 + tx];
    __syncthreads();
    __nv_bfloat16* dh = out_hi + (size_t)e * R * C;
    __nv_bfloat16* dl = out_lo + (size_t)e * R * C;
    #pragma unroll
    for (int i = ty; i < 32; i += 8) {
        float v = tile[tx][i];
        __nv_bfloat16 h = __float2bfloat16(v);
        __nv_bfloat16 l = __float2bfloat16(v - __bfloat162float(h));
        dh[(size_t)(c0 + i) * R + r0 + tx] = h;
        dl[(size_t)(c0 + i) * R + r0 + tx] = l;
    }
}

__global__ __launch_bounds__(256) void prep_kernel(
    const float* __restrict__ tokens, const float* __restrict__ gate_w,
    const float* __restrict__ w1, const float* __restrict__ w2,
    float* __restrict__ out)
{
    __shared__ __align__(16) char sbuf[16384];
    __shared__ float s_load[N_EXP];
    __shared__ int   s_cnt[N_EXP];
    __shared__ float s_z;
    int b = blockIdx.x;
    int t = threadIdx.x;

    if (b >= NB_GATE) {
        float (*tile)[33] = (float(*)[33])sbuf;
        int tx = t & 31, ty = t >> 5;
        if (b < NB_GATE + NB_W1T) {
            int idx = b - NB_GATE;
            int e = idx >> 10, rem = idx & 1023;
            int c0 = (rem & 63) * 32, r0 = (rem >> 6) * 32;
            transpose_split_part(tile, w1, g_w1T_hi, g_w1T_lo, D_MODEL, F_FF, e, c0, r0, tx, ty);
        } else {
            int idx = b - NB_GATE - NB_W1T;
            int e = idx >> 10, rem = idx & 1023;
            int c0 = (rem & 15) * 32, r0 = (rem >> 4) * 32;
            transpose_split_part(tile, w2, g_w2T_hi, g_w2T_lo, F_FF, D_MODEL, e, c0, r0, tx, ty);
        }
        return;
    }

    float* gwT = (float*)sbuf;   // [8][512]
    for (int i = t; i < D_MODEL * N_EXP; i += 256) {
        int d = i >> 3, e = i & 7;
        gwT[e * 512 + d] = gate_w[i];
    }
    if (t < N_EXP) { s_load[t] = 0.0f; s_cnt[t] = 0; }
    if (t == 0) s_z = 0.0f;
    __syncthreads();

    int n0 = b * 8;
    {
        const float4* src = (const float4*)(tokens + (size_t)n0 * D_MODEL);
        size_t obase = (size_t)n0 * D_MODEL;
        for (int i = t; i < 1024; i += 256) {
            float4 v = src[i];
            __nv_bfloat16 h0 = __float2bfloat16(v.x), h1 = __float2bfloat16(v.y);
            __nv_bfloat16 h2 = __float2bfloat16(v.z), h3 = __float2bfloat16(v.w);
            __nv_bfloat16 l0 = __float2bfloat16(v.x - __bfloat162float(h0));
            __nv_bfloat16 l1 = __float2bfloat16(v.y - __bfloat162float(h1));
            __nv_bfloat16 l2 = __float2bfloat16(v.z - __bfloat162float(h2));
            __nv_bfloat16 l3 = __float2bfloat16(v.w - __bfloat162float(h3));
            __nv_bfloat162 ph0, ph1, pl0, pl1;
            ph0.x = h0; ph0.y = h1; ph1.x = h2; ph1.y = h3;
            pl0.x = l0; pl0.y = l1; pl1.x = l2; pl1.y = l3;
            ((__nv_bfloat162*)(g_tok_hi + obase))[2*i]   = ph0;
            ((__nv_bfloat162*)(g_tok_hi + obase))[2*i+1] = ph1;
            ((__nv_bfloat162*)(g_tok_lo + obase))[2*i]   = pl0;
            ((__nv_bfloat162*)(g_tok_lo + obase))[2*i+1] = pl1;
        }
    }

    int warp = t >> 5, lane = t & 31;
    int n = n0 + warp;
    const float* x = tokens + (size_t)n * D_MODEL;

    float acc[8] = {0.f,0.f,0.f,0.f,0.f,0.f,0.f,0.f};
    for (int d = lane; d < D_MODEL; d += 32) {
        float xv = x[d];
        #pragma unroll
        for (int e = 0; e < 8; e++) acc[e] = fmaf(xv, gwT[e * 512 + d], acc[e]);
    }
    #pragma unroll
    for (int e = 0; e < 8; e++) {
        #pragma unroll
        for (int o = 16; o; o >>= 1)
            acc[e] += __shfl_down_sync(0xffffffffu, acc[e], o);
    }

    if (lane == 0) {
        float m = acc[0];
        #pragma unroll
        for (int e = 1; e < 8; e++) m = fmaxf(m, acc[e]);
        float p[8], s = 0.0f;
        #pragma unroll
        for (int e = 0; e < 8; e++) { p[e] = expf(acc[e] - m); s += p[e]; }
        float inv = 1.0f / s;
        #pragma unroll
        for (int e = 0; e < 8; e++) p[e] *= inv;

        float* gl = out + OUT_LOGITS + (size_t)n * N_EXP;
        float* pr = out + OUT_PROBS  + (size_t)n * N_EXP;
        #pragma unroll
        for (int e = 0; e < 8; e++) { gl[e] = acc[e]; pr[e] = p[e]; }

        float lse = m + logf(s);
        atomicAdd(&s_z, lse * lse);
        #pragma unroll
        for (int e = 0; e < 8; e++) atomicAdd(&s_load[e], p[e]);

        int i0 = 0; float m0 = p[0];
        #pragma unroll
        for (int e = 1; e < 8; e++) if (p[e] > m0) { m0 = p[e]; i0 = e; }
        int i1 = (i0 == 0) ? 1 : 0; float m1 = p[i1];
        #pragma unroll
        for (int e = 0; e < 8; e++)
            if (e != i0 && p[e] > m1) { m1 = p[e]; i1 = e; }
        float ws = m0 + m1;
        g_topk_idx[2 * n]     = i0;
        g_topk_idx[2 * n + 1] = i1;
        g_topk_w[2 * n]       = m0 / ws;
        g_topk_w[2 * n + 1]   = m1 / ws;
        atomicAdd(&s_cnt[i0], 1);
        atomicAdd(&s_cnt[i1], 1);
    }
    __syncthreads();
    if (t < N_EXP) {
        atomicAdd(&g_cnt[t], s_cnt[t]);
        atomicAdd(&g_loadsum[t], s_load[t]);
    }
    if (t == 0) atomicAdd(&g_zsum, s_z);
}

// ---------------- finalize ----------------
__global__ void finalize_kernel(float* __restrict__ out) {
    if (threadIdx.x != 0) return;
    int off = 0;
    float lb = 0.0f;
    int tcount = 0;
    for (int e = 0; e < N_EXP; e++) {
        g_cursor[e] = off;
        int cnt = g_cnt[e];
        float load = g_loadsum[e] / (float)N_TOK;
        out[OUT_LOAD + e] = load;
        out[OUT_CNT + e]  = (float)cnt;
        lb += ((float)cnt / (float)N_ASSIGN) * load;
        for (int r = 0; r < cnt; r += BM) {
            g_tile_e[tcount]    = e;
            g_tile_p0[tcount]   = off + r;
            int rem = cnt - r;
            g_tile_rows[tcount] = rem < BM ? rem : BM;
            tcount++;
        }
        off += cnt;
    }
    for (int i = tcount; i < NT_TILES; i++) g_tile_rows[i] = 0;
    out[OUT_LB] = (float)N_EXP * lb;
    out[OUT_Z]  = g_zsum / (float)N_TOK;
}

// ---------------- scatter ----------------
__global__ void scatter_kernel() {
    int n = blockIdx.x * blockDim.x + threadIdx.x;
    if (n >= N_TOK) return;
    #pragma unroll
    for (int k = 0; k < 2; k++) {
        int e = g_topk_idx[2 * n + k];
        int pos = atomicAdd(&g_cursor[e], 1);
        g_tok[pos] = n;
        g_pos[2 * n + k] = pos;
    }
}

// =============== fused-limb warp-MMA GEMMs ===============
// CTA 128x128, 8 warps 2(M)x4(N), warp tile 64x32. BK=32 per stage; each smem row
// holds hi(64B)|lo(64B)|pad(16B). Per k16: ldsm Ah/Al/Bh/Bl, then 3 MMA combos.

// GEMM1: hidden = gelu(gather(tokens) @ w1T^T + b1) -> split bf16 hi/lo
__global__ __launch_bounds__(256, 2) void gemm1_mma(const float* __restrict__ b1) {
    int tile = blockIdx.x;
    int rows = g_tile_rows[tile];
    if (rows == 0) return;
    int e = g_tile_e[tile], p0 = g_tile_p0[tile];
    int c0 = blockIdx.y * BN;

    extern __shared__ char dyn[];
    int*   s_tok  = (int*)(dyn + STOK_OFF);
    float* s_bias = (float*)(dyn + SBIAS_OFF);

    int t = threadIdx.x, wid = t >> 5, lane = t & 31;
    if (t < BM) {
        int rr = (t < rows) ? t : (rows - 1);
        s_tok[t]  = g_tok[p0 + rr];
        s_bias[t] = b1[(size_t)e * F_FF + c0 + t];
    }
    __syncthreads();

    uint32_t sb = smem_u32(dyn);
    uint32_t sA[3] = {sb, sb + SA_ST, sb + 2 * SA_ST};
    uint32_t sB[3] = {sb + 3 * SA_ST, sb + 4 * SA_ST, sb + 5 * SA_ST};

    auto loadStage = [&](int kt, int st) {
        int kk = kt * BK;
        #pragma unroll
        for (int it = 0; it < 4; it++) {
            int idx = t + it * 256;
            int row = idx >> 3, c = idx & 7;
            const __nv_bfloat16* src = (c < 4)
                ? g_tok_hi + (size_t)s_tok[row] * D_MODEL + kk + c * 8
                : g_tok_lo + (size_t)s_tok[row] * D_MODEL + kk + (c - 4) * 8;
            CP_ASYNC16(sA[st] + row * LDAB + ((c < 4) ? c * 16 : 64 + (c - 4) * 16), src);
        }
        const __nv_bfloat16* Bh = g_w1T_hi + ((size_t)e * F_FF + c0) * D_MODEL + kk;
        const __nv_bfloat16* Bl = g_w1T_lo + ((size_t)e * F_FF + c0) * D_MODEL + kk;
        #pragma unroll
        for (int it = 0; it < 4; it++) {
            int idx = t + it * 256;
            int row = idx >> 3, c = idx & 7;
            const __nv_bfloat16* src = (c < 4)
                ? Bh + (size_t)row * D_MODEL + c * 8
                : Bl + (size_t)row * D_MODEL + (c - 4) * 8;
            CP_ASYNC16(sB[st] + row * LDAB + ((c < 4) ? c * 16 : 64 + (c - 4) * 16), src);
        }
        CP_COMMIT();
    };

    int wm = (wid >> 2) * 64, wn = (wid & 3) * 32;
    uint32_t aOff = (uint32_t)((wm + (lane & 15)) * LDAB + (lane >> 4) * 16);
    uint32_t bOff = (uint32_t)((wn + (lane & 15)) * LDAB + (lane >> 4) * 16);

    float acc[4][4][4];
    #pragma unroll
    for (int i = 0; i < 4; i++)
        #pragma unroll
        for (int j = 0; j < 4; j++)
            #pragma unroll
            for (int r = 0; r < 4; r++) acc[i][j][r] = 0.0f;

    const int KT = D_MODEL / BK;   // 16
    loadStage(0, 0);
    loadStage(1, 1);
    #pragma unroll 1
    for (int kt = 0; kt < KT; kt++) {
        if (kt + 1 < KT) { CP_WAIT1(); } else { CP_WAIT0(); }
        __syncthreads();
        if (kt + 2 < KT) loadStage(kt + 2, (kt + 2) % 3);
        int st = kt % 3;
        uint32_t aB = sA[st] + aOff, bB = sB[st] + bOff;

        #pragma unroll
        for (int j = 0; j < 2; j++) {          // k16 sub-chunks
            uint32_t ah[4][4], al[4][4], bh[2][4], bl[2][4];
            #pragma unroll
            for (int mt = 0; mt < 4; mt++) {
                ldsm_x4(aB + mt * 16 * LDAB + j * 32,
                        ah[mt][0], ah[mt][1], ah[mt][2], ah[mt][3]);
                ldsm_x4(aB + mt * 16 * LDAB + 64 + j * 32,
                        al[mt][0], al[mt][1], al[mt][2], al[mt][3]);
            }
            #pragma unroll
            for (int p = 0; p < 2; p++) {
                ldsm_x4(bB + p * 16 * LDAB + j * 32,
                        bh[p][0], bh[p][1], bh[p][2], bh[p][3]);
                ldsm_x4(bB + p * 16 * LDAB + 64 + j * 32,
                        bl[p][0], bl[p][1], bl[p][2], bl[p][3]);
            }
            #pragma unroll
            for (int mt = 0; mt < 4; mt++)
                #pragma unroll
                for (int nt = 0; nt < 4; nt++)
                    mma_bf16(acc[mt][nt], ah[mt], bh[nt >> 1][nt & 1], bh[nt >> 1][(nt & 1) + 2]);
            #pragma unroll
            for (int mt = 0; mt < 4; mt++)
                #pragma unroll
                for (int nt = 0; nt < 4; nt++)
                    mma_bf16(acc[mt][nt], ah[mt], bl[nt >> 1][nt & 1], bl[nt >> 1][(nt & 1) + 2]);
            #pragma unroll
            for (int mt = 0; mt < 4; mt++)
                #pragma unroll
                for (int nt = 0; nt < 4; nt++)
                    mma_bf16(acc[mt][nt], al[mt], bh[nt >> 1][nt & 1], bh[nt >> 1][(nt & 1) + 2]);
        }
    }

    int qrow = lane >> 2, qcol = (lane & 3) * 2;
    #pragma unroll
    for (int mt = 0; mt < 4; mt++) {
        #pragma unroll
        for (int half = 0; half < 2; half++) {
            int m = wm + mt * 16 + qrow + 8 * half;
            if (m >= rows) continue;
            size_t orow = (size_t)(p0 + m) * F_FF + c0;
            #pragma unroll
            for (int nt = 0; nt < 4; nt++) {
                int nl = wn + nt * 8 + qcol;
                float v0 = gelu_f(acc[mt][nt][2 * half]     + s_bias[nl]);
                float v1 = gelu_f(acc[mt][nt][2 * half + 1] + s_bias[nl + 1]);
                __nv_bfloat16 h0 = __float2bfloat16(v0), h1 = __float2bfloat16(v1);
                __nv_bfloat16 l0 = __float2bfloat16(v0 - __bfloat162float(h0));
                __nv_bfloat16 l1 = __float2bfloat16(v1 - __bfloat162float(h1));
                __nv_bfloat162 ph, pl;
                ph.x = h0; ph.y = h1; pl.x = l0; pl.y = l1;
                *(__nv_bfloat162*)(g_hid_hi + orow + nl) = ph;
                *(__nv_bfloat162*)(g_hid_lo + orow + nl) = pl;
            }
        }
    }
}

// GEMM2 (split-K=2): y[half] = hidden[:, Khalf] @ w2T^T (+ b2 on half 0)
__global__ __launch_bounds__(256, 2) void gemm2_mma(const float* __restrict__ b2) {
    int tile = blockIdx.x;
    int rows = g_tile_rows[tile];
    if (rows == 0) return;
    int e = g_tile_e[tile], p0 = g_tile_p0[tile];
    int c0 = blockIdx.y * BN;
    int khalf = blockIdx.z;

    extern __shared__ char dyn[];
    float* s_bias = (float*)(dyn + SBIAS_OFF);

    int t = threadIdx.x, wid = t >> 5, lane = t & 31;
    if (t < BN) s_bias[t] = khalf ? 0.0f : b2[(size_t)e * D_MODEL + c0 + t];
    __syncthreads();

    uint32_t sb = smem_u32(dyn);
    uint32_t sA[3] = {sb, sb + SA_ST, sb + 2 * SA_ST};
    uint32_t sB[3] = {sb + 3 * SA_ST, sb + 4 * SA_ST, sb + 5 * SA_ST};

    auto loadStage = [&](int kt, int st) {
        int kk = kt * BK;
        const __nv_bfloat16* Ah = g_hid_hi + (size_t)p0 * F_FF + kk;
        const __nv_bfloat16* Al = g_hid_lo + (size_t)p0 * F_FF + kk;
        const __nv_bfloat16* Bh = g_w2T_hi + ((size_t)e * D_MODEL + c0) * F_FF + kk;
        const __nv_bfloat16* Bl = g_w2T_lo + ((size_t)e * D_MODEL + c0) * F_FF + kk;
        #pragma unroll
        for (int it = 0; it < 4; it++) {
            int idx = t + it * 256;
            int row = idx >> 3, c = idx & 7;
            const __nv_bfloat16* src = (c < 4)
                ? Ah + (size_t)row * F_FF + c * 8
                : Al + (size_t)row * F_FF + (c - 4) * 8;
            CP_ASYNC16(sA[st] + row * LDAB + ((c < 4) ? c * 16 : 64 + (c - 4) * 16), src);
        }
        #pragma unroll
        for (int it = 0; it < 4; it++) {
            int idx = t + it * 256;
            int row = idx >> 3, c = idx & 7;
            const __nv_bfloat16* src = (c < 4)
                ? Bh + (size_t)row * F_FF + c * 8
                : Bl + (size_t)row * F_FF + (c - 4) * 8;
            CP_ASYNC16(sB[st] + row * LDAB + ((c < 4) ? c * 16 : 64 + (c - 4) * 16), src);
        }
        CP_COMMIT();
    };

    int wm = (wid >> 2) * 64, wn = (wid & 3) * 32;
    uint32_t aOff = (uint32_t)((wm + (lane & 15)) * LDAB + (lane >> 4) * 16);
    uint32_t bOff = (uint32_t)((wn + (lane & 15)) * LDAB + (lane >> 4) * 16);

    float acc[4][4][4];
    #pragma unroll
    for (int i = 0; i < 4; i++)
        #pragma unroll
        for (int j = 0; j < 4; j++)
            #pragma unroll
            for (int r = 0; r < 4; r++) acc[i][j][r] = 0.0f;

    const int KT_HALF = (F_FF / BK) / 2;   // 32
    int kbase = khalf * KT_HALF;
    loadStage(kbase + 0, 0);
    loadStage(kbase + 1, 1);
    #pragma unroll 1
    for (int kt = 0; kt < KT_HALF; kt++) {
        if (kt + 1 < KT_HALF) { CP_WAIT1(); } else { CP_WAIT0(); }
        __syncthreads();
        if (kt + 2 < KT_HALF) loadStage(kbase + kt + 2, (kt + 2) % 3);
        int st = kt % 3;
        uint32_t aB = sA[st] + aOff, bB = sB[st] + bOff;

        #pragma unroll
        for (int j = 0; j < 2; j++) {
            uint32_t ah[4][4], al[4][4], bh[2][4], bl[2][4];
            #pragma unroll
            for (int mt = 0; mt < 4; mt++) {
                ldsm_x4(aB + mt * 16 * LDAB + j * 32,
                        ah[mt][0], ah[mt][1], ah[mt][2], ah[mt][3]);
                ldsm_x4(aB + mt * 16 * LDAB + 64 + j * 32,
                        al[mt][0], al[mt][1], al[mt][2], al[mt][3]);
            }
            #pragma unroll
            for (int p = 0; p < 2; p++) {
                ldsm_x4(bB + p * 16 * LDAB + j * 32,
                        bh[p][0], bh[p][1], bh[p][2], bh[p][3]);
                ldsm_x4(bB + p * 16 * LDAB + 64 + j * 32,
                        bl[p][0], bl[p][1], bl[p][2], bl[p][3]);
            }
            #pragma unroll
            for (int mt = 0; mt < 4; mt++)
                #pragma unroll
                for (int nt = 0; nt < 4; nt++)
                    mma_bf16(acc[mt][nt], ah[mt], bh[nt >> 1][nt & 1], bh[nt >> 1][(nt & 1) + 2]);
            #pragma unroll
            for (int mt = 0; mt < 4; mt++)
                #pragma unroll
                for (int nt = 0; nt < 4; nt++)
                    mma_bf16(acc[mt][nt], ah[mt], bl[nt >> 1][nt & 1], bl[nt >> 1][(nt & 1) + 2]);
            #pragma unroll
            for (int mt = 0; mt < 4; mt++)
                #pragma unroll
                for (int nt = 0; nt < 4; nt++)
                    mma_bf16(acc[mt][nt], al[mt], bh[nt >> 1][nt & 1], bh[nt >> 1][(nt & 1) + 2]);
        }
    }

    float* yout = khalf ? g_y2 : g_y;
    int qrow = lane >> 2, qcol = (lane & 3) * 2;
    #pragma unroll
    for (int mt = 0; mt < 4; mt++) {
        #pragma unroll
        for (int half = 0; half < 2; half++) {
            int m = wm + mt * 16 + qrow + 8 * half;
            if (m >= rows) continue;
            size_t orow = (size_t)(p0 + m) * D_MODEL + c0;
            #pragma unroll
            for (int nt = 0; nt < 4; nt++) {
                int nl = wn + nt * 8 + qcol;
                float2 v;
                v.x = acc[mt][nt][2 * half]     + s_bias[nl];
                v.y = acc[mt][nt][2 * half + 1] + s_bias[nl + 1];
                *(float2*)(yout + orow + nl) = v;
            }
        }
    }
}

// ---------------- combine: out = w0*(yA+yB)[p0] + w1*(yA+yB)[p1] ----------------
__global__ __launch_bounds__(128) void combine_kernel(float* __restrict__ out) {
    int n = blockIdx.x;
    int pa = g_pos[2 * n], pb = g_pos[2 * n + 1];
    float w0 = g_topk_w[2 * n], w1 = g_topk_w[2 * n + 1];
    int d = threadIdx.x * 4;
    float4 ya0 = *(const float4*)(g_y  + (size_t)pa * D_MODEL + d);
    float4 yb0 = *(const float4*)(g_y2 + (size_t)pa * D_MODEL + d);
    float4 ya1 = *(const float4*)(g_y  + (size_t)pb * D_MODEL + d);
    float4 yb1 = *(const float4*)(g_y2 + (size_t)pb * D_MODEL + d);
    float4 r;
    r.x = w0 * (ya0.x + yb0.x) + w1 * (ya1.x + yb1.x);
    r.y = w0 * (ya0.y + yb0.y) + w1 * (ya1.y + yb1.y);
    r.z = w0 * (ya0.z + yb0.z) + w1 * (ya1.z + yb1.z);
    r.w = w0 * (ya0.w + yb0.w) + w1 * (ya1.w + yb1.w);
    *(float4*)(out + (size_t)n * D_MODEL + d) = r;
}

// ---------------- launch ----------------
extern "C" void kernel_launch(void* const* d_in, const int* in_sizes, int n_in,
                              void* d_out, int out_size) {
    const float* h_t    = (const float*)d_in[0];
    const float* gate_w = (const float*)d_in[1];
    const float* w1     = (const float*)d_in[2];
    const float* b1     = (const float*)d_in[3];
    const float* w2     = (const float*)d_in[4];
    const float* b2     = (const float*)d_in[5];
    float* out = (float*)d_out;

    cudaFuncSetAttribute(gemm1_mma, cudaFuncAttributeMaxDynamicSharedMemorySize, SMEM_BYTES);
    cudaFuncSetAttribute(gemm2_mma, cudaFuncAttributeMaxDynamicSharedMemorySize, SMEM_BYTES);

    init_kernel<<<1, 32>>>();
    prep_kernel<<<NB_GATE + NB_W1T + NB_W2T, 256>>>(h_t, gate_w, w1, w2, out);
    finalize_kernel<<<1, 32>>>(out);
    scatter_kernel<<<N_TOK / 256, 256>>>();
    gemm1_mma<<<dim3(NT_TILES, F_FF / BN), 256, SMEM_BYTES>>>(b1);
    gemm2_mma<<<dim3(NT_TILES, D_MODEL / BN, 2), 256, SMEM_BYTES>>>(b2);
    combine_kernel<<<N_TOK, 128>>>(out);
}

// round 11
// speedup vs baseline: 2.5974x; 1.0100x over previous
#include <cuda_runtime.h>
#include <cuda_bf16.h>
#include <math.h>
#include <stdint.h>

#define D_MODEL 512
#define F_FF    2048
#define N_EXP   8
#define N_TOK   8192
#define N_ASSIGN (N_TOK * 2)
#define NT_TILES 160
#define BM 128
#define BN 128
#define BK 32            // K elems per stage (each row carries hi+lo limbs)
#define LDAB 144         // smem row: 64B hi | 64B lo | 16B pad

#define SA_ST (BM * LDAB)                 // 18432
#define STOK_OFF  (6 * SA_ST)             // 110592 (3 A stages + 3 B stages)
#define SBIAS_OFF (STOK_OFF + 512)
#define SMEM_BYTES (SBIAS_OFF + 512)      // 111616

// prep block partition
#define NB_GATE 1024
#define NB_W1T  8192
#define NB_W2T  8192

#define OUT_LOGITS ((size_t)N_TOK * D_MODEL)
#define OUT_PROBS  (OUT_LOGITS + (size_t)N_TOK * N_EXP)
#define OUT_Z      (OUT_PROBS + (size_t)N_TOK * N_EXP)
#define OUT_LB     (OUT_Z + 1)
#define OUT_LOAD   (OUT_LB + 1)
#define OUT_CNT    (OUT_LOAD + N_EXP)

// ---------------- static scratch ----------------
__device__ __nv_bfloat16 g_tok_hi[N_TOK * D_MODEL];
__device__ __nv_bfloat16 g_tok_lo[N_TOK * D_MODEL];
__device__ __nv_bfloat16 g_w1T_hi[N_EXP * F_FF * D_MODEL];   // [E, F, D] K-major
__device__ __nv_bfloat16 g_w1T_lo[N_EXP * F_FF * D_MODEL];
__device__ __nv_bfloat16 g_w2T_hi[N_EXP * D_MODEL * F_FF];   // [E, D, F] K-major
__device__ __nv_bfloat16 g_w2T_lo[N_EXP * D_MODEL * F_FF];
__device__ __nv_bfloat16 g_hid_hi[(N_ASSIGN + BM) * F_FF];
__device__ __nv_bfloat16 g_hid_lo[(N_ASSIGN + BM) * F_FF];
__device__ float g_y [(size_t)(N_ASSIGN + BM) * D_MODEL];
__device__ float g_y2[(size_t)(N_ASSIGN + BM) * D_MODEL];
__device__ int   g_tok[N_ASSIGN + BM];
__device__ int   g_pos[N_ASSIGN];
__device__ int   g_topk_idx[N_ASSIGN];
__device__ float g_topk_w[N_ASSIGN];
__device__ int   g_cnt[N_EXP];
__device__ int   g_cursor[N_EXP];
__device__ float g_zsum;
__device__ float g_loadsum[N_EXP];
__device__ int   g_tile_e[NT_TILES];
__device__ int   g_tile_p0[NT_TILES];
__device__ int   g_tile_rows[NT_TILES];

// ---------------- PTX helpers (baseline ISA only) ----------------
__device__ __forceinline__ uint32_t smem_u32(const void* p) {
    uint32_t a;
    asm("{ .reg .u64 t; cvta.to.shared.u64 t, %1; cvt.u32.u64 %0, t; }" : "=r"(a) : "l"(p));
    return a;
}
#define CP_ASYNC16(dst, src) \
    asm volatile("cp.async.cg.shared.global [%0], [%1], 16;" :: "r"(dst), "l"(src) : "memory")
#define CP_COMMIT() asm volatile("cp.async.commit_group;" ::: "memory")
#define CP_WAIT1()  asm volatile("cp.async.wait_group 1;" ::: "memory")
#define CP_WAIT0()  asm volatile("cp.async.wait_group 0;" ::: "memory")

__device__ __forceinline__ void ldsm_x4(uint32_t addr, uint32_t& r0, uint32_t& r1,
                                        uint32_t& r2, uint32_t& r3) {
    asm volatile("ldmatrix.sync.aligned.m8n8.x4.shared.b16 {%0,%1,%2,%3}, [%4];"
        : "=r"(r0), "=r"(r1), "=r"(r2), "=r"(r3) : "r"(addr));
}
__device__ __forceinline__ void mma_bf16(float* d, const uint32_t* a,
                                         uint32_t b0, uint32_t b1) {
    asm volatile(
        "mma.sync.aligned.m16n8k16.row.col.f32.bf16.bf16.f32 "
        "{%0,%1,%2,%3}, {%4,%5,%6,%7}, {%8,%9}, {%0,%1,%2,%3};"
        : "+f"(d[0]), "+f"(d[1]), "+f"(d[2]), "+f"(d[3])
        : "r"(a[0]), "r"(a[1]), "r"(a[2]), "r"(a[3]), "r"(b0), "r"(b1));
}
// fast gelu: tanh(u) = 1 - 2/(1+exp(2u)) via MUFU ex2/rcp. Saturates correctly
// (exp->inf => tanh->1, exp->0 => tanh->-1). rel err ~1e-6, negligible vs 1e-3.
__device__ __forceinline__ float gelu_f(float x) {
    const float c = 0.7978845608028654f;
    float u = c * (x + 0.044715f * x * x * x);
    float e = __expf(2.0f * u);
    float t = 1.0f - __fdividef(2.0f, e + 1.0f);
    return 0.5f * x * (1.0f + t);
}

// ---------------- init ----------------
__global__ void init_kernel() {
    int t = threadIdx.x;
    if (t < N_EXP) { g_cnt[t] = 0; g_loadsum[t] = 0.0f; }
    if (t == 0) g_zsum = 0.0f;
}

// ================ prep: gating(+stats) + token split + weight transposes ================
__device__ __forceinline__ void transpose_split_part(
    float (*tile)[33], const float* __restrict__ in,
    __nv_bfloat16* __restrict__ out_hi, __nv_bfloat16* __restrict__ out_lo,
    int R, int C, int e, int c0, int r0, int tx, int ty)
{
    const float* src = in + (size_t)e * R * C;
    #pragma unroll
    for (int i = ty; i < 32; i += 8)
        tile[i][tx] = src[(size_t)(r0 + i) * C + c0 + tx];
    __syncthreads();
    __nv_bfloat16* dh = out_hi + (size_t)e * R * C;
    __nv_bfloat16* dl = out_lo + (size_t)e * R * C;
    #pragma unroll
    for (int i = ty; i < 32; i += 8) {
        float v = tile[tx][i];
        __nv_bfloat16 h = __float2bfloat16(v);
        __nv_bfloat16 l = __float2bfloat16(v - __bfloat162float(h));
        dh[(size_t)(c0 + i) * R + r0 + tx] = h;
        dl[(size_t)(c0 + i) * R + r0 + tx] = l;
    }
}

__global__ __launch_bounds__(256) void prep_kernel(
    const float* __restrict__ tokens, const float* __restrict__ gate_w,
    const float* __restrict__ w1, const float* __restrict__ w2,
    float* __restrict__ out)
{
    __shared__ __align__(16) char sbuf[16384];
    __shared__ float s_load[N_EXP];
    __shared__ int   s_cnt[N_EXP];
    __shared__ float s_z;
    int b = blockIdx.x;
    int t = threadIdx.x;

    if (b >= NB_GATE) {
        float (*tile)[33] = (float(*)[33])sbuf;
        int tx = t & 31, ty = t >> 5;
        if (b < NB_GATE + NB_W1T) {
            int idx = b - NB_GATE;
            int e = idx >> 10, rem = idx & 1023;
            int c0 = (rem & 63) * 32, r0 = (rem >> 6) * 32;
            transpose_split_part(tile, w1, g_w1T_hi, g_w1T_lo, D_MODEL, F_FF, e, c0, r0, tx, ty);
        } else {
            int idx = b - NB_GATE - NB_W1T;
            int e = idx >> 10, rem = idx & 1023;
            int c0 = (rem & 15) * 32, r0 = (rem >> 4) * 32;
            transpose_split_part(tile, w2, g_w2T_hi, g_w2T_lo, F_FF, D_MODEL, e, c0, r0, tx, ty);
        }
        return;
    }

    float* gwT = (float*)sbuf;   // [8][512]
    for (int i = t; i < D_MODEL * N_EXP; i += 256) {
        int d = i >> 3, e = i & 7;
        gwT[e * 512 + d] = gate_w[i];
    }
    if (t < N_EXP) { s_load[t] = 0.0f; s_cnt[t] = 0; }
    if (t == 0) s_z = 0.0f;
    __syncthreads();

    int n0 = b * 8;
    {
        const float4* src = (const float4*)(tokens + (size_t)n0 * D_MODEL);
        size_t obase = (size_t)n0 * D_MODEL;
        for (int i = t; i < 1024; i += 256) {
            float4 v = src[i];
            __nv_bfloat16 h0 = __float2bfloat16(v.x), h1 = __float2bfloat16(v.y);
            __nv_bfloat16 h2 = __float2bfloat16(v.z), h3 = __float2bfloat16(v.w);
            __nv_bfloat16 l0 = __float2bfloat16(v.x - __bfloat162float(h0));
            __nv_bfloat16 l1 = __float2bfloat16(v.y - __bfloat162float(h1));
            __nv_bfloat16 l2 = __float2bfloat16(v.z - __bfloat162float(h2));
            __nv_bfloat16 l3 = __float2bfloat16(v.w - __bfloat162float(h3));
            __nv_bfloat162 ph0, ph1, pl0, pl1;
            ph0.x = h0; ph0.y = h1; ph1.x = h2; ph1.y = h3;
            pl0.x = l0; pl0.y = l1; pl1.x = l2; pl1.y = l3;
            ((__nv_bfloat162*)(g_tok_hi + obase))[2*i]   = ph0;
            ((__nv_bfloat162*)(g_tok_hi + obase))[2*i+1] = ph1;
            ((__nv_bfloat162*)(g_tok_lo + obase))[2*i]   = pl0;
            ((__nv_bfloat162*)(g_tok_lo + obase))[2*i+1] = pl1;
        }
    }

    int warp = t >> 5, lane = t & 31;
    int n = n0 + warp;
    const float* x = tokens + (size_t)n * D_MODEL;

    float acc[8] = {0.f,0.f,0.f,0.f,0.f,0.f,0.f,0.f};
    for (int d = lane; d < D_MODEL; d += 32) {
        float xv = x[d];
        #pragma unroll
        for (int e = 0; e < 8; e++) acc[e] = fmaf(xv, gwT[e * 512 + d], acc[e]);
    }
    #pragma unroll
    for (int e = 0; e < 8; e++) {
        #pragma unroll
        for (int o = 16; o; o >>= 1)
            acc[e] += __shfl_down_sync(0xffffffffu, acc[e], o);
    }

    if (lane == 0) {
        float m = acc[0];
        #pragma unroll
        for (int e = 1; e < 8; e++) m = fmaxf(m, acc[e]);
        float p[8], s = 0.0f;
        #pragma unroll
        for (int e = 0; e < 8; e++) { p[e] = expf(acc[e] - m); s += p[e]; }
        float inv = 1.0f / s;
        #pragma unroll
        for (int e = 0; e < 8; e++) p[e] *= inv;

        float* gl = out + OUT_LOGITS + (size_t)n * N_EXP;
        float* pr = out + OUT_PROBS  + (size_t)n * N_EXP;
        #pragma unroll
        for (int e = 0; e < 8; e++) { gl[e] = acc[e]; pr[e] = p[e]; }

        float lse = m + logf(s);
        atomicAdd(&s_z, lse * lse);
        #pragma unroll
        for (int e = 0; e < 8; e++) atomicAdd(&s_load[e], p[e]);

        int i0 = 0; float m0 = p[0];
        #pragma unroll
        for (int e = 1; e < 8; e++) if (p[e] > m0) { m0 = p[e]; i0 = e; }
        int i1 = (i0 == 0) ? 1 : 0; float m1 = p[i1];
        #pragma unroll
        for (int e = 0; e < 8; e++)
            if (e != i0 && p[e] > m1) { m1 = p[e]; i1 = e; }
        float ws = m0 + m1;
        g_topk_idx[2 * n]     = i0;
        g_topk_idx[2 * n + 1] = i1;
        g_topk_w[2 * n]       = m0 / ws;
        g_topk_w[2 * n + 1]   = m1 / ws;
        atomicAdd(&s_cnt[i0], 1);
        atomicAdd(&s_cnt[i1], 1);
    }
    __syncthreads();
    if (t < N_EXP) {
        atomicAdd(&g_cnt[t], s_cnt[t]);
        atomicAdd(&g_loadsum[t], s_load[t]);
    }
    if (t == 0) atomicAdd(&g_zsum, s_z);
}

// ---------------- finalize ----------------
__global__ void finalize_kernel(float* __restrict__ out) {
    if (threadIdx.x != 0) return;
    int off = 0;
    float lb = 0.0f;
    int tcount = 0;
    for (int e = 0; e < N_EXP; e++) {
        g_cursor[e] = off;
        int cnt = g_cnt[e];
        float load = g_loadsum[e] / (float)N_TOK;
        out[OUT_LOAD + e] = load;
        out[OUT_CNT + e]  = (float)cnt;
        lb += ((float)cnt / (float)N_ASSIGN) * load;
        for (int r = 0; r < cnt; r += BM) {
            g_tile_e[tcount]    = e;
            g_tile_p0[tcount]   = off + r;
            int rem = cnt - r;
            g_tile_rows[tcount] = rem < BM ? rem : BM;
            tcount++;
        }
        off += cnt;
    }
    for (int i = tcount; i < NT_TILES; i++) g_tile_rows[i] = 0;
    out[OUT_LB] = (float)N_EXP * lb;
    out[OUT_Z]  = g_zsum / (float)N_TOK;
}

// ---------------- scatter ----------------
__global__ void scatter_kernel() {
    int n = blockIdx.x * blockDim.x + threadIdx.x;
    if (n >= N_TOK) return;
    #pragma unroll
    for (int k = 0; k < 2; k++) {
        int e = g_topk_idx[2 * n + k];
        int pos = atomicAdd(&g_cursor[e], 1);
        g_tok[pos] = n;
        g_pos[2 * n + k] = pos;
    }
}

// =============== fused-limb warp-MMA GEMMs ===============
// CTA 128x128, 8 warps 2(M)x4(N), warp tile 64x32. BK=32 per stage; each smem row
// holds hi(64B)|lo(64B)|pad(16B). Per k16: ldsm Ah/Al/Bh/Bl, then 3 MMA combos.

// GEMM1: hidden = gelu(gather(tokens) @ w1T^T + b1) -> split bf16 hi/lo
__global__ __launch_bounds__(256, 2) void gemm1_mma(const float* __restrict__ b1) {
    int tile = blockIdx.x;
    int rows = g_tile_rows[tile];
    if (rows == 0) return;
    int e = g_tile_e[tile], p0 = g_tile_p0[tile];
    int c0 = blockIdx.y * BN;

    extern __shared__ char dyn[];
    int*   s_tok  = (int*)(dyn + STOK_OFF);
    float* s_bias = (float*)(dyn + SBIAS_OFF);

    int t = threadIdx.x, wid = t >> 5, lane = t & 31;
    if (t < BM) {
        int rr = (t < rows) ? t : (rows - 1);
        s_tok[t]  = g_tok[p0 + rr];
        s_bias[t] = b1[(size_t)e * F_FF + c0 + t];
    }
    __syncthreads();

    uint32_t sb = smem_u32(dyn);
    uint32_t sA[3] = {sb, sb + SA_ST, sb + 2 * SA_ST};
    uint32_t sB[3] = {sb + 3 * SA_ST, sb + 4 * SA_ST, sb + 5 * SA_ST};

    auto loadStage = [&](int kt, int st) {
        int kk = kt * BK;
        #pragma unroll
        for (int it = 0; it < 4; it++) {
            int idx = t + it * 256;
            int row = idx >> 3, c = idx & 7;
            const __nv_bfloat16* src = (c < 4)
                ? g_tok_hi + (size_t)s_tok[row] * D_MODEL + kk + c * 8
                : g_tok_lo + (size_t)s_tok[row] * D_MODEL + kk + (c - 4) * 8;
            CP_ASYNC16(sA[st] + row * LDAB + ((c < 4) ? c * 16 : 64 + (c - 4) * 16), src);
        }
        const __nv_bfloat16* Bh = g_w1T_hi + ((size_t)e * F_FF + c0) * D_MODEL + kk;
        const __nv_bfloat16* Bl = g_w1T_lo + ((size_t)e * F_FF + c0) * D_MODEL + kk;
        #pragma unroll
        for (int it = 0; it < 4; it++) {
            int idx = t + it * 256;
            int row = idx >> 3, c = idx & 7;
            const __nv_bfloat16* src = (c < 4)
                ? Bh + (size_t)row * D_MODEL + c * 8
                : Bl + (size_t)row * D_MODEL + (c - 4) * 8;
            CP_ASYNC16(sB[st] + row * LDAB + ((c < 4) ? c * 16 : 64 + (c - 4) * 16), src);
        }
        CP_COMMIT();
    };

    int wm = (wid >> 2) * 64, wn = (wid & 3) * 32;
    uint32_t aOff = (uint32_t)((wm + (lane & 15)) * LDAB + (lane >> 4) * 16);
    uint32_t bOff = (uint32_t)((wn + (lane & 15)) * LDAB + (lane >> 4) * 16);

    float acc[4][4][4];
    #pragma unroll
    for (int i = 0; i < 4; i++)
        #pragma unroll
        for (int j = 0; j < 4; j++)
            #pragma unroll
            for (int r = 0; r < 4; r++) acc[i][j][r] = 0.0f;

    const int KT = D_MODEL / BK;   // 16
    loadStage(0, 0);
    loadStage(1, 1);
    #pragma unroll 1
    for (int kt = 0; kt < KT; kt++) {
        if (kt + 1 < KT) { CP_WAIT1(); } else { CP_WAIT0(); }
        __syncthreads();
        if (kt + 2 < KT) loadStage(kt + 2, (kt + 2) % 3);
        int st = kt % 3;
        uint32_t aB = sA[st] + aOff, bB = sB[st] + bOff;

        #pragma unroll
        for (int j = 0; j < 2; j++) {          // k16 sub-chunks
            uint32_t ah[4][4], al[4][4], bh[2][4], bl[2][4];
            #pragma unroll
            for (int mt = 0; mt < 4; mt++) {
                ldsm_x4(aB + mt * 16 * LDAB + j * 32,
                        ah[mt][0], ah[mt][1], ah[mt][2], ah[mt][3]);
                ldsm_x4(aB + mt * 16 * LDAB + 64 + j * 32,
                        al[mt][0], al[mt][1], al[mt][2], al[mt][3]);
            }
            #pragma unroll
            for (int p = 0; p < 2; p++) {
                ldsm_x4(bB + p * 16 * LDAB + j * 32,
                        bh[p][0], bh[p][1], bh[p][2], bh[p][3]);
                ldsm_x4(bB + p * 16 * LDAB + 64 + j * 32,
                        bl[p][0], bl[p][1], bl[p][2], bl[p][3]);
            }
            #pragma unroll
            for (int mt = 0; mt < 4; mt++)
                #pragma unroll
                for (int nt = 0; nt < 4; nt++)
                    mma_bf16(acc[mt][nt], ah[mt], bh[nt >> 1][nt & 1], bh[nt >> 1][(nt & 1) + 2]);
            #pragma unroll
            for (int mt = 0; mt < 4; mt++)
                #pragma unroll
                for (int nt = 0; nt < 4; nt++)
                    mma_bf16(acc[mt][nt], ah[mt], bl[nt >> 1][nt & 1], bl[nt >> 1][(nt & 1) + 2]);
            #pragma unroll
            for (int mt = 0; mt < 4; mt++)
                #pragma unroll
                for (int nt = 0; nt < 4; nt++)
                    mma_bf16(acc[mt][nt], al[mt], bh[nt >> 1][nt & 1], bh[nt >> 1][(nt & 1) + 2]);
        }
    }

    int qrow = lane >> 2, qcol = (lane & 3) * 2;
    #pragma unroll
    for (int mt = 0; mt < 4; mt++) {
        #pragma unroll
        for (int half = 0; half < 2; half++) {
            int m = wm + mt * 16 + qrow + 8 * half;
            if (m >= rows) continue;
            size_t orow = (size_t)(p0 + m) * F_FF + c0;
            #pragma unroll
            for (int nt = 0; nt < 4; nt++) {
                int nl = wn + nt * 8 + qcol;
                float v0 = gelu_f(acc[mt][nt][2 * half]     + s_bias[nl]);
                float v1 = gelu_f(acc[mt][nt][2 * half + 1] + s_bias[nl + 1]);
                __nv_bfloat16 h0 = __float2bfloat16(v0), h1 = __float2bfloat16(v1);
                __nv_bfloat16 l0 = __float2bfloat16(v0 - __bfloat162float(h0));
                __nv_bfloat16 l1 = __float2bfloat16(v1 - __bfloat162float(h1));
                __nv_bfloat162 ph, pl;
                ph.x = h0; ph.y = h1; pl.x = l0; pl.y = l1;
                *(__nv_bfloat162*)(g_hid_hi + orow + nl) = ph;
                *(__nv_bfloat162*)(g_hid_lo + orow + nl) = pl;
            }
        }
    }
}

// GEMM2 (split-K=2): y[half] = hidden[:, Khalf] @ w2T^T (+ b2 on half 0)
__global__ __launch_bounds__(256, 2) void gemm2_mma(const float* __restrict__ b2) {
    int tile = blockIdx.x;
    int rows = g_tile_rows[tile];
    if (rows == 0) return;
    int e = g_tile_e[tile], p0 = g_tile_p0[tile];
    int c0 = blockIdx.y * BN;
    int khalf = blockIdx.z;

    extern __shared__ char dyn[];
    float* s_bias = (float*)(dyn + SBIAS_OFF);

    int t = threadIdx.x, wid = t >> 5, lane = t & 31;
    if (t < BN) s_bias[t] = khalf ? 0.0f : b2[(size_t)e * D_MODEL + c0 + t];
    __syncthreads();

    uint32_t sb = smem_u32(dyn);
    uint32_t sA[3] = {sb, sb + SA_ST, sb + 2 * SA_ST};
    uint32_t sB[3] = {sb + 3 * SA_ST, sb + 4 * SA_ST, sb + 5 * SA_ST};

    auto loadStage = [&](int kt, int st) {
        int kk = kt * BK;
        const __nv_bfloat16* Ah = g_hid_hi + (size_t)p0 * F_FF + kk;
        const __nv_bfloat16* Al = g_hid_lo + (size_t)p0 * F_FF + kk;
        const __nv_bfloat16* Bh = g_w2T_hi + ((size_t)e * D_MODEL + c0) * F_FF + kk;
        const __nv_bfloat16* Bl = g_w2T_lo + ((size_t)e * D_MODEL + c0) * F_FF + kk;
        #pragma unroll
        for (int it = 0; it < 4; it++) {
            int idx = t + it * 256;
            int row = idx >> 3, c = idx & 7;
            const __nv_bfloat16* src = (c < 4)
                ? Ah + (size_t)row * F_FF + c * 8
                : Al + (size_t)row * F_FF + (c - 4) * 8;
            CP_ASYNC16(sA[st] + row * LDAB + ((c < 4) ? c * 16 : 64 + (c - 4) * 16), src);
        }
        #pragma unroll
        for (int it = 0; it < 4; it++) {
            int idx = t + it * 256;
            int row = idx >> 3, c = idx & 7;
            const __nv_bfloat16* src = (c < 4)
                ? Bh + (size_t)row * F_FF + c * 8
                : Bl + (size_t)row * F_FF + (c - 4) * 8;
            CP_ASYNC16(sB[st] + row * LDAB + ((c < 4) ? c * 16 : 64 + (c - 4) * 16), src);
        }
        CP_COMMIT();
    };

    int wm = (wid >> 2) * 64, wn = (wid & 3) * 32;
    uint32_t aOff = (uint32_t)((wm + (lane & 15)) * LDAB + (lane >> 4) * 16);
    uint32_t bOff = (uint32_t)((wn + (lane & 15)) * LDAB + (lane >> 4) * 16);

    float acc[4][4][4];
    #pragma unroll
    for (int i = 0; i < 4; i++)
        #pragma unroll
        for (int j = 0; j < 4; j++)
            #pragma unroll
            for (int r = 0; r < 4; r++) acc[i][j][r] = 0.0f;

    const int KT_HALF = (F_FF / BK) / 2;   // 32
    int kbase = khalf * KT_HALF;
    loadStage(kbase + 0, 0);
    loadStage(kbase + 1, 1);
    #pragma unroll 1
    for (int kt = 0; kt < KT_HALF; kt++) {
        if (kt + 1 < KT_HALF) { CP_WAIT1(); } else { CP_WAIT0(); }
        __syncthreads();
        if (kt + 2 < KT_HALF) loadStage(kbase + kt + 2, (kt + 2) % 3);
        int st = kt % 3;
        uint32_t aB = sA[st] + aOff, bB = sB[st] + bOff;

        #pragma unroll
        for (int j = 0; j < 2; j++) {
            uint32_t ah[4][4], al[4][4], bh[2][4], bl[2][4];
            #pragma unroll
            for (int mt = 0; mt < 4; mt++) {
                ldsm_x4(aB + mt * 16 * LDAB + j * 32,
                        ah[mt][0], ah[mt][1], ah[mt][2], ah[mt][3]);
                ldsm_x4(aB + mt * 16 * LDAB + 64 + j * 32,
                        al[mt][0], al[mt][1], al[mt][2], al[mt][3]);
            }
            #pragma unroll
            for (int p = 0; p < 2; p++) {
                ldsm_x4(bB + p * 16 * LDAB + j * 32,
                        bh[p][0], bh[p][1], bh[p][2], bh[p][3]);
                ldsm_x4(bB + p * 16 * LDAB + 64 + j * 32,
                        bl[p][0], bl[p][1], bl[p][2], bl[p][3]);
            }
            #pragma unroll
            for (int mt = 0; mt < 4; mt++)
                #pragma unroll
                for (int nt = 0; nt < 4; nt++)
                    mma_bf16(acc[mt][nt], ah[mt], bh[nt >> 1][nt & 1], bh[nt >> 1][(nt & 1) + 2]);
            #pragma unroll
            for (int mt = 0; mt < 4; mt++)
                #pragma unroll
                for (int nt = 0; nt < 4; nt++)
                    mma_bf16(acc[mt][nt], ah[mt], bl[nt >> 1][nt & 1], bl[nt >> 1][(nt & 1) + 2]);
            #pragma unroll
            for (int mt = 0; mt < 4; mt++)
                #pragma unroll
                for (int nt = 0; nt < 4; nt++)
                    mma_bf16(acc[mt][nt], al[mt], bh[nt >> 1][nt & 1], bh[nt >> 1][(nt & 1) + 2]);
        }
    }

    float* yout = khalf ? g_y2 : g_y;
    int qrow = lane >> 2, qcol = (lane & 3) * 2;
    #pragma unroll
    for (int mt = 0; mt < 4; mt++) {
        #pragma unroll
        for (int half = 0; half < 2; half++) {
            int m = wm + mt * 16 + qrow + 8 * half;
            if (m >= rows) continue;
            size_t orow = (size_t)(p0 + m) * D_MODEL + c0;
            #pragma unroll
            for (int nt = 0; nt < 4; nt++) {
                int nl = wn + nt * 8 + qcol;
                float2 v;
                v.x = acc[mt][nt][2 * half]     + s_bias[nl];
                v.y = acc[mt][nt][2 * half + 1] + s_bias[nl + 1];
                *(float2*)(yout + orow + nl) = v;
            }
        }
    }
}

// ---------------- combine: out = w0*(yA+yB)[p0] + w1*(yA+yB)[p1] ----------------
__global__ __launch_bounds__(128) void combine_kernel(float* __restrict__ out) {
    int n = blockIdx.x;
    int pa = g_pos[2 * n], pb = g_pos[2 * n + 1];
    float w0 = g_topk_w[2 * n], w1 = g_topk_w[2 * n + 1];
    int d = threadIdx.x * 4;
    float4 ya0 = *(const float4*)(g_y  + (size_t)pa * D_MODEL + d);
    float4 yb0 = *(const float4*)(g_y2 + (size_t)pa * D_MODEL + d);
    float4 ya1 = *(const float4*)(g_y  + (size_t)pb * D_MODEL + d);
    float4 yb1 = *(const float4*)(g_y2 + (size_t)pb * D_MODEL + d);
    float4 r;
    r.x = w0 * (ya0.x + yb0.x) + w1 * (ya1.x + yb1.x);
    r.y = w0 * (ya0.y + yb0.y) + w1 * (ya1.y + yb1.y);
    r.z = w0 * (ya0.z + yb0.z) + w1 * (ya1.z + yb1.z);
    r.w = w0 * (ya0.w + yb0.w) + w1 * (ya1.w + yb1.w);
    *(float4*)(out + (size_t)n * D_MODEL + d) = r;
}

// ---------------- launch ----------------
extern "C" void kernel_launch(void* const* d_in, const int* in_sizes, int n_in,
                              void* d_out, int out_size) {
    const float* h_t    = (const float*)d_in[0];
    const float* gate_w = (const float*)d_in[1];
    const float* w1     = (const float*)d_in[2];
    const float* b1     = (const float*)d_in[3];
    const float* w2     = (const float*)d_in[4];
    const float* b2     = (const float*)d_in[5];
    float* out = (float*)d_out;

    cudaFuncSetAttribute(gemm1_mma, cudaFuncAttributeMaxDynamicSharedMemorySize, SMEM_BYTES);
    cudaFuncSetAttribute(gemm2_mma, cudaFuncAttributeMaxDynamicSharedMemorySize, SMEM_BYTES);

    init_kernel<<<1, 32>>>();
    prep_kernel<<<NB_GATE + NB_W1T + NB_W2T, 256>>>(h_t, gate_w, w1, w2, out);
    finalize_kernel<<<1, 32>>>(out);
    scatter_kernel<<<N_TOK / 256, 256>>>();
    gemm1_mma<<<dim3(NT_TILES, F_FF / BN), 256, SMEM_BYTES>>>(b1);
    gemm2_mma<<<dim3(NT_TILES, D_MODEL / BN, 2), 256, SMEM_BYTES>>>(b2);
    combine_kernel<<<N_TOK, 128>>>(out);
}